// round 9
// baseline (speedup 1.0000x reference)
#include <cuda_runtime.h>
#include <math_constants.h>
#include <cstdint>

// Problem shape (fixed by setup_inputs): x[4,256,64,64]
#define BB   4
#define CDIM 256
#define NDIM 4096
#define C8   32

// ---------------- scratch (static device globals; no allocation) -------------
// Q/K stored pre-split into tf32 high/low parts, k-interleaved per 8-chunk.
__device__ float g_Qh[BB * NDIM * C8];
__device__ float g_Ql[BB * NDIM * C8];
__device__ float g_Kh[BB * NDIM * C8];
__device__ float g_Kl[BB * NDIM * C8];
__device__ float g_V [BB * NDIM * CDIM];  // V[b][j][c] raw fp32
__device__ float g_V2[BB * CDIM * NDIM];  // V[b][c][j], tf32-rounded, j-interleaved

// =============================================================================
// helpers
// =============================================================================
__device__ __forceinline__ uint32_t smem_u32(const void* p) {
    uint32_t a;
    asm("{ .reg .u64 t; cvta.to.shared.u64 t, %1; cvt.u32.u64 %0, t; }" : "=r"(a) : "l"(p));
    return a;
}
__device__ __forceinline__ uint32_t f2tf(float x) {
    uint32_t r;
    asm("cvt.rna.tf32.f32 %0, %1;" : "=r"(r) : "f"(x));
    return r;
}
// interleave within 8-chunk: k -> 2*(k&3) + ((k&4)>>2)
__device__ __forceinline__ int kperm(int c) {
    return (c & ~7) + 2 * (c & 3) + ((c & 4) >> 2);
}
// smem bank swizzle: XOR float-col by 8*(row&3); conflict-free for all
// fragment LDS.64 phases (bank = 8*(kst^lg) + 2*l4, distinct per 16-lane phase)
#define SWZ(r, c) ((c) ^ (8 * ((r) & 3)))

__device__ __forceinline__ void mma_tf32(float c[4], uint32_t a0, uint32_t a1,
                                         uint32_t a2, uint32_t a3,
                                         uint32_t b0, uint32_t b1) {
    asm volatile(
        "mma.sync.aligned.m16n8k8.row.col.f32.tf32.tf32.f32 "
        "{%0,%1,%2,%3}, {%4,%5,%6,%7}, {%8,%9}, {%0,%1,%2,%3};"
        : "+f"(c[0]), "+f"(c[1]), "+f"(c[2]), "+f"(c[3])
        : "r"(a0), "r"(a1), "r"(a2), "r"(a3), "r"(b0), "r"(b1));
}
__device__ __forceinline__ void cpa16(uint32_t dst, const void* src) {
    asm volatile("cp.async.cg.shared.global [%0], [%1], 16;" :: "r"(dst), "l"(src) : "memory");
}
#define CP_COMMIT() asm volatile("cp.async.commit_group;" ::: "memory")
#define CP_WAIT0()  asm volatile("cp.async.wait_group 0;" ::: "memory")

// =============================================================================
// Projection. sel 0/1 (Q/K, O=32): write tf32 high/low split, k-interleaved.
// sel 2 (V, O=256): raw float4 to g_V.
// =============================================================================
__global__ __launch_bounds__(256) void proj_kernel(
    const float* __restrict__ x, const float* __restrict__ Wm,
    const float* __restrict__ bias, int O, int sel)
{
    __shared__ float Xs[16][128];
    __shared__ float Ws[16][64];

    const int b  = blockIdx.z;
    const int i0 = blockIdx.x * 128;
    const int o0 = blockIdx.y * 64;
    const int t  = threadIdx.x;
    const int tx = t & 15;
    const int ty = t >> 4;

    const float* xb = x + (size_t)b * CDIM * NDIM;

    float acc[8][4];
#pragma unroll
    for (int r = 0; r < 8; r++)
#pragma unroll
        for (int u = 0; u < 4; u++) acc[r][u] = 0.f;

    for (int c0 = 0; c0 < CDIM; c0 += 16) {
#pragma unroll
        for (int l = t; l < 512; l += 256) {
            int r = l >> 5, q = l & 31;
            float4 v = *reinterpret_cast<const float4*>(xb + (size_t)(c0 + r) * NDIM + i0 + q * 4);
            *reinterpret_cast<float4*>(&Xs[r][q * 4]) = v;
        }
        {
            int o = t >> 2, c4 = (t & 3) * 4;
            float4 w = make_float4(0.f, 0.f, 0.f, 0.f);
            if (o0 + o < O)
                w = *reinterpret_cast<const float4*>(Wm + (size_t)(o0 + o) * CDIM + c0 + c4);
            Ws[c4 + 0][o] = w.x; Ws[c4 + 1][o] = w.y;
            Ws[c4 + 2][o] = w.z; Ws[c4 + 3][o] = w.w;
        }
        __syncthreads();
#pragma unroll
        for (int cc = 0; cc < 16; cc++) {
            float4 a0 = *reinterpret_cast<const float4*>(&Xs[cc][ty * 8]);
            float4 a1 = *reinterpret_cast<const float4*>(&Xs[cc][ty * 8 + 4]);
            float4 bv = *reinterpret_cast<const float4*>(&Ws[cc][tx * 4]);
            float aa[8] = {a0.x, a0.y, a0.z, a0.w, a1.x, a1.y, a1.z, a1.w};
            float bb[4] = {bv.x, bv.y, bv.z, bv.w};
#pragma unroll
            for (int r = 0; r < 8; r++)
#pragma unroll
                for (int u = 0; u < 4; u++) acc[r][u] += aa[r] * bb[u];
        }
        __syncthreads();
    }

    if (o0 + tx * 4 < O) {
        float4 bs = *reinterpret_cast<const float4*>(bias + o0 + tx * 4);
        float bb[4] = {bs.x, bs.y, bs.z, bs.w};
        if (sel == 2) {
#pragma unroll
            for (int r = 0; r < 8; r++) {
                float4 v = make_float4(acc[r][0] + bb[0], acc[r][1] + bb[1],
                                       acc[r][2] + bb[2], acc[r][3] + bb[3]);
                *reinterpret_cast<float4*>(g_V + ((size_t)b * NDIM + i0 + ty * 8 + r) * O + o0 + tx * 4) = v;
            }
        } else {
            float* Oh = (sel == 0) ? g_Qh : g_Kh;
            float* Ol = (sel == 0) ? g_Ql : g_Kl;
#pragma unroll
            for (int r = 0; r < 8; r++) {
                const size_t row = ((size_t)b * NDIM + i0 + ty * 8 + r) * 32;
#pragma unroll
                for (int u = 0; u < 4; u++) {
                    float v = acc[r][u] + bb[u];
                    float hf = __uint_as_float(f2tf(v));
                    float lf = __uint_as_float(f2tf(v - hf));
                    int pos = kperm(tx * 4 + u);   // o0 == 0 for O=32
                    Oh[row + pos] = hf;
                    Ol[row + pos] = lf;
                }
            }
        }
    }
}

// =============================================================================
// Transpose V: g_V[b][j][c] -> g_V2[b][c][perm(j)], tf32-rounded
// =============================================================================
__global__ __launch_bounds__(256) void transpose_v_kernel()
{
    __shared__ float ts[32][33];
    const int j0 = blockIdx.x * 32;
    const int c0 = blockIdx.y * 32;
    const int b  = blockIdx.z;
    const int tx = threadIdx.x;
    const int ty = threadIdx.y;
#pragma unroll
    for (int k = 0; k < 4; k++)
        ts[ty + 8 * k][tx] = g_V[((size_t)b * NDIM + j0 + ty + 8 * k) * CDIM + c0 + tx];
    __syncthreads();
    const int jp = j0 + kperm(tx);
#pragma unroll
    for (int k = 0; k < 4; k++)
        g_V2[((size_t)b * CDIM + c0 + ty + 8 * k) * NDIM + jp] =
            __uint_as_float(f2tf(ts[tx][ty + 8 * k]));
}

// =============================================================================
// tf32 mma.sync flash attention, 2 CTAs/SM (114.9 KB smem), single wave.
// CTA = 64 queries x 256 threads. No max-subtraction (|logit| <= ~35).
// Single-buffered K/V with split fills: K(tl+1) issued after S (K dead),
// V(tl+1) after PV (V dead); latency hidden by the co-resident CTA.
// smem floats (all swizzled, no pad): Qh/Ql 2x2048 | Kh/Kl 2x2048 |
//   V 256x64 | S 64x64 | den 64  = 28736 fl = 114,944 B
// =============================================================================
#define QH_OFF  0
#define QL_OFF  2048
#define KH_OFF  4096
#define KL_OFF  6144
#define V_OFF   8192
#define S_OFF   24576
#define DEN_OFF 28672
#define SMEM_FLOATS 28736
#define SMEM_ATTN (SMEM_FLOATS * 4)   // 114944 B

__global__ __launch_bounds__(256, 2) void attn_kernel(
    const float* __restrict__ x, const float* __restrict__ gamma,
    float* __restrict__ out)
{
    extern __shared__ float smf[];
    const uint32_t sb = smem_u32(smf);
    const int t  = threadIdx.x;
    const int w  = t >> 5;
    const int lg = (t & 31) >> 2;
    const int l4 = t & 3;
    const int b  = blockIdx.y;
    const int i0 = blockIdx.x * 64;

    // ---- Q preload (split+interleaved in gmem) into swizzled smem ----
#pragma unroll
    for (int it = 0; it < 2; it++) {
        int idx = it * 256 + t;           // 512 16B-chunks per part
        int r = idx >> 3, q = idx & 7;
        const size_t gsrc = ((size_t)(b * NDIM + i0 + r) << 5) + q * 4;
        const int dc = SWZ(r, q * 4);
        *reinterpret_cast<float4*>(&smf[QH_OFF + r * 32 + dc]) =
            *reinterpret_cast<const float4*>(g_Qh + gsrc);
        *reinterpret_cast<float4*>(&smf[QL_OFF + r * 32 + dc]) =
            *reinterpret_cast<const float4*>(g_Ql + gsrc);
    }

    auto fillK = [&](int tl) {
        const int j0 = tl << 6;
#pragma unroll
        for (int it = 0; it < 2; it++) {
            int idx = it * 256 + t;
            int r = idx >> 3, q = idx & 7;
            const size_t gsrc = ((size_t)(b * NDIM + j0 + r) << 5) + q * 4;
            const int dc = SWZ(r, q * 4);
            cpa16(sb + (KH_OFF + r * 32 + dc) * 4, g_Kh + gsrc);
            cpa16(sb + (KL_OFF + r * 32 + dc) * 4, g_Kl + gsrc);
        }
        CP_COMMIT();
    };
    auto fillV = [&](int tl) {
        const int j0 = tl << 6;
#pragma unroll
        for (int it = 0; it < 16; it++) {
            int idx = it * 256 + t;
            int cr = idx >> 4, q = idx & 15;
            cpa16(sb + (V_OFF + cr * 64 + SWZ(cr, q * 4)) * 4,
                  g_V2 + ((size_t)(b * CDIM + cr) << 12) + j0 + q * 4);
        }
        CP_COMMIT();
    };

    fillK(0);
    fillV(0);

    // PV: warp tile rows pm0..+31, cols pn0..+63
    const int pm0 = (w & 1) * 32;
    const int pn0 = (w >> 1) * 64;
    float acc[2][8][4];
#pragma unroll
    for (int mt = 0; mt < 2; mt++)
#pragma unroll
        for (int nt = 0; nt < 8; nt++)
#pragma unroll
            for (int u = 0; u < 4; u++) acc[mt][nt][u] = 0.f;

    // QK: warp tile rows qm0..+15, cols qn0..+31
    const int qm0 = (w & 3) * 16;
    const int qn0 = (w >> 2) * 32;

    // softmax ownership: thread owns row sr, cols sc..sc+15
    const int sr = t >> 2;
    const int sc = (t & 3) * 16;
    float den = 0.f;

    for (int tl = 0; tl < 64; tl++) {
        CP_WAIT0();
        __syncthreads();                         // B1: K,V of tile tl visible

        // ---- S = Q.K^T, 3-term tf32 split ----
        {
            float sfrag[4][4];
#pragma unroll
            for (int nt = 0; nt < 4; nt++)
#pragma unroll
                for (int u = 0; u < 4; u++) sfrag[nt][u] = 0.f;

#pragma unroll
            for (int kst = 0; kst < 4; kst++) {
                const int k0 = kst * 8 + 2 * l4;
                const int asw = SWZ(lg, k0);
                uint2 ah0 = *reinterpret_cast<const uint2*>(&smf[QH_OFF + (qm0 + lg)     * 32 + asw]);
                uint2 ah1 = *reinterpret_cast<const uint2*>(&smf[QH_OFF + (qm0 + lg + 8) * 32 + asw]);
                uint2 al0 = *reinterpret_cast<const uint2*>(&smf[QL_OFF + (qm0 + lg)     * 32 + asw]);
                uint2 al1 = *reinterpret_cast<const uint2*>(&smf[QL_OFF + (qm0 + lg + 8) * 32 + asw]);
#pragma unroll
                for (int nt = 0; nt < 4; nt++) {
                    const int jr = qn0 + nt * 8 + lg;
                    uint2 bh = *reinterpret_cast<const uint2*>(&smf[KH_OFF + jr * 32 + asw]);
                    uint2 bl = *reinterpret_cast<const uint2*>(&smf[KL_OFF + jr * 32 + asw]);
                    mma_tf32(sfrag[nt], ah0.x, ah1.x, ah0.y, ah1.y, bh.x, bh.y);
                    mma_tf32(sfrag[nt], ah0.x, ah1.x, ah0.y, ah1.y, bl.x, bl.y);
                    mma_tf32(sfrag[nt], al0.x, al1.x, al0.y, al1.y, bh.x, bh.y);
                }
            }
#pragma unroll
            for (int nt = 0; nt < 4; nt++) {
                const int col = qn0 + nt * 8 + 2 * l4;
                *reinterpret_cast<float2*>(&smf[S_OFF + (qm0 + lg) * 64 + SWZ(lg, col)]) =
                    make_float2(sfrag[nt][0], sfrag[nt][1]);
                *reinterpret_cast<float2*>(&smf[S_OFF + (qm0 + lg + 8) * 64 + SWZ(lg, col)]) =
                    make_float2(sfrag[nt][2], sfrag[nt][3]);
            }
        }
        __syncthreads();                         // B2: S done, K buffer dead
        if (tl < 63) fillK(tl + 1);              // prefetch K overlaps exp+PV

        // ---- P = tf32(exp(S)) written k-interleaved; den += rowsum ----
        {
            float p[16];
            float rsum = 0.f;
#pragma unroll
            for (int i = 0; i < 4; i++) {
                float4 v = *reinterpret_cast<const float4*>(
                    &smf[S_OFF + sr * 64 + SWZ(sr, sc + 4 * i)]);
                p[4*i+0] = __uint_as_float(f2tf(__expf(v.x)));
                p[4*i+1] = __uint_as_float(f2tf(__expf(v.y)));
                p[4*i+2] = __uint_as_float(f2tf(__expf(v.z)));
                p[4*i+3] = __uint_as_float(f2tf(__expf(v.w)));
                rsum += p[4*i+0] + p[4*i+1] + p[4*i+2] + p[4*i+3];
            }
            rsum += __shfl_xor_sync(0xffffffffu, rsum, 1);
            rsum += __shfl_xor_sync(0xffffffffu, rsum, 2);
            den += rsum;
#pragma unroll
            for (int c2 = 0; c2 < 2; c2++)
#pragma unroll
                for (int j = 0; j < 4; j++)
                    *reinterpret_cast<float2*>(
                        &smf[S_OFF + sr * 64 + SWZ(sr, sc + c2 * 8 + 2 * j)]) =
                        make_float2(p[c2 * 8 + j], p[c2 * 8 + j + 4]);
        }
        __syncthreads();                         // B3: P complete

        // ---- OUT += P.V ----
        {
#pragma unroll
            for (int kst = 0; kst < 8; kst++) {
                const int k0 = kst * 8 + 2 * l4;
                const int ksw = SWZ(lg, k0);
                uint2 pa[2][2];
#pragma unroll
                for (int mt = 0; mt < 2; mt++) {
                    const int r0 = pm0 + mt * 16;
                    pa[mt][0] = *reinterpret_cast<const uint2*>(&smf[S_OFF + (r0 + lg)     * 64 + ksw]);
                    pa[mt][1] = *reinterpret_cast<const uint2*>(&smf[S_OFF + (r0 + lg + 8) * 64 + ksw]);
                }
#pragma unroll
                for (int nt = 0; nt < 8; nt++) {
                    const int cr = pn0 + nt * 8 + lg;
                    uint2 bv = *reinterpret_cast<const uint2*>(&smf[V_OFF + cr * 64 + ksw]);
                    mma_tf32(acc[0][nt], pa[0][0].x, pa[0][1].x, pa[0][0].y, pa[0][1].y, bv.x, bv.y);
                    mma_tf32(acc[1][nt], pa[1][0].x, pa[1][1].x, pa[1][0].y, pa[1][1].y, bv.x, bv.y);
                }
            }
        }
        __syncthreads();                         // B0: PV done, V buffer dead
        if (tl < 63) fillV(tl + 1);              // prefetch V overlaps next QK
    }

    // ---- epilogue ----
    if ((t & 3) == 0) smf[DEN_OFF + sr] = den;
    __syncthreads();

    const float ga = gamma[0];
    const float* xb = x   + (size_t)b * CDIM * NDIM;
    float*       ob = out + (size_t)b * CDIM * NDIM;

#pragma unroll
    for (int mt = 0; mt < 2; mt++) {
        const int r0 = pm0 + mt * 16;
        const float inv0 = 1.f / smf[DEN_OFF + r0 + lg];
        const float inv1 = 1.f / smf[DEN_OFF + r0 + lg + 8];
        const int gi0 = i0 + r0 + lg;
#pragma unroll
        for (int nt = 0; nt < 8; nt++) {
            const int col = pn0 + nt * 8 + 2 * l4;
            const size_t b00 = (size_t)col * NDIM + gi0;
            const size_t b10 = b00 + NDIM;
            ob[b00]     = ga * (acc[mt][nt][0] * inv0) + xb[b00];
            ob[b10]     = ga * (acc[mt][nt][1] * inv0) + xb[b10];
            ob[b00 + 8] = ga * (acc[mt][nt][2] * inv1) + xb[b00 + 8];
            ob[b10 + 8] = ga * (acc[mt][nt][3] * inv1) + xb[b10 + 8];
        }
    }
}

// =============================================================================
extern "C" void kernel_launch(void* const* d_in, const int* in_sizes, int n_in,
                              void* d_out, int out_size)
{
    (void)in_sizes; (void)n_in; (void)out_size;
    const float* x     = (const float*)d_in[0];
    const float* Wq    = (const float*)d_in[1];
    const float* bq    = (const float*)d_in[2];
    const float* Wk    = (const float*)d_in[3];
    const float* bk    = (const float*)d_in[4];
    const float* Wv    = (const float*)d_in[5];
    const float* bv    = (const float*)d_in[6];
    const float* gamma = (const float*)d_in[7];
    float* out = (float*)d_out;

    (void)cudaFuncSetAttribute(attn_kernel,
                               cudaFuncAttributeMaxDynamicSharedMemorySize, SMEM_ATTN);

    dim3 gq(NDIM / 128, 1, BB);
    dim3 gv(NDIM / 128, 4, BB);
    proj_kernel<<<gq, 256>>>(x, Wq, bq, C8,   0);
    proj_kernel<<<gq, 256>>>(x, Wk, bk, C8,   1);
    proj_kernel<<<gv, 256>>>(x, Wv, bv, CDIM, 2);

    dim3 gt(NDIM / 32, CDIM / 32, BB);
    transpose_v_kernel<<<gt, dim3(32, 8)>>>();

    dim3 ga(NDIM / 64, BB);    // 256 CTAs, 2 per SM -> single wave
    attn_kernel<<<ga, 256, SMEM_ATTN>>>(x, gamma, out);
}

// round 10
// speedup vs baseline: 1.0090x; 1.0090x over previous
#include <cuda_runtime.h>
#include <math_constants.h>
#include <cstdint>

// Problem shape (fixed by setup_inputs): x[4,256,64,64]
#define BB   4
#define CDIM 256
#define NDIM 4096
#define C8   32

// ---------------- scratch (static device globals; no allocation) -------------
// Q/K stored pre-split into tf32 high/low parts, k-interleaved per 8-chunk.
__device__ float g_Qh[BB * NDIM * C8];
__device__ float g_Ql[BB * NDIM * C8];
__device__ float g_Kh[BB * NDIM * C8];
__device__ float g_Kl[BB * NDIM * C8];
__device__ float g_V [BB * NDIM * CDIM];  // V[b][j][c] raw fp32
__device__ float g_V2[BB * CDIM * NDIM];  // V[b][c][j], tf32-rounded, j-interleaved

// =============================================================================
// helpers
// =============================================================================
__device__ __forceinline__ uint32_t smem_u32(const void* p) {
    uint32_t a;
    asm("{ .reg .u64 t; cvta.to.shared.u64 t, %1; cvt.u32.u64 %0, t; }" : "=r"(a) : "l"(p));
    return a;
}
__device__ __forceinline__ uint32_t f2tf(float x) {
    uint32_t r;
    asm("cvt.rna.tf32.f32 %0, %1;" : "=r"(r) : "f"(x));
    return r;
}
// interleave within 8-chunk: k -> 2*(k&3) + ((k&4)>>2)
__device__ __forceinline__ int kperm(int c) {
    return (c & ~7) + 2 * (c & 3) + ((c & 4) >> 2);
}
// smem bank swizzle: XOR float-col by 8*(row&3); conflict-free for all
// fragment LDS.64 phases
#define SWZ(r, c) ((c) ^ (8 * ((r) & 3)))

__device__ __forceinline__ void mma_tf32(float c[4], uint32_t a0, uint32_t a1,
                                         uint32_t a2, uint32_t a3,
                                         uint32_t b0, uint32_t b1) {
    asm volatile(
        "mma.sync.aligned.m16n8k8.row.col.f32.tf32.tf32.f32 "
        "{%0,%1,%2,%3}, {%4,%5,%6,%7}, {%8,%9}, {%0,%1,%2,%3};"
        : "+f"(c[0]), "+f"(c[1]), "+f"(c[2]), "+f"(c[3])
        : "r"(a0), "r"(a1), "r"(a2), "r"(a3), "r"(b0), "r"(b1));
}
__device__ __forceinline__ void cpa16(uint32_t dst, const void* src) {
    asm volatile("cp.async.cg.shared.global [%0], [%1], 16;" :: "r"(dst), "l"(src) : "memory");
}
#define CP_COMMIT() asm volatile("cp.async.commit_group;" ::: "memory")
#define CP_WAIT1()  asm volatile("cp.async.wait_group 1;" ::: "memory")
#define CP_WAIT0()  asm volatile("cp.async.wait_group 0;" ::: "memory")

// =============================================================================
// Projection. sel 0/1 (Q/K, O=32): write tf32 high/low split, k-interleaved.
// sel 2 (V, O=256): raw float4 to g_V.
// =============================================================================
__global__ __launch_bounds__(256) void proj_kernel(
    const float* __restrict__ x, const float* __restrict__ Wm,
    const float* __restrict__ bias, int O, int sel)
{
    __shared__ float Xs[16][128];
    __shared__ float Ws[16][64];

    const int b  = blockIdx.z;
    const int i0 = blockIdx.x * 128;
    const int o0 = blockIdx.y * 64;
    const int t  = threadIdx.x;
    const int tx = t & 15;
    const int ty = t >> 4;

    const float* xb = x + (size_t)b * CDIM * NDIM;

    float acc[8][4];
#pragma unroll
    for (int r = 0; r < 8; r++)
#pragma unroll
        for (int u = 0; u < 4; u++) acc[r][u] = 0.f;

    for (int c0 = 0; c0 < CDIM; c0 += 16) {
#pragma unroll
        for (int l = t; l < 512; l += 256) {
            int r = l >> 5, q = l & 31;
            float4 v = *reinterpret_cast<const float4*>(xb + (size_t)(c0 + r) * NDIM + i0 + q * 4);
            *reinterpret_cast<float4*>(&Xs[r][q * 4]) = v;
        }
        {
            int o = t >> 2, c4 = (t & 3) * 4;
            float4 w = make_float4(0.f, 0.f, 0.f, 0.f);
            if (o0 + o < O)
                w = *reinterpret_cast<const float4*>(Wm + (size_t)(o0 + o) * CDIM + c0 + c4);
            Ws[c4 + 0][o] = w.x; Ws[c4 + 1][o] = w.y;
            Ws[c4 + 2][o] = w.z; Ws[c4 + 3][o] = w.w;
        }
        __syncthreads();
#pragma unroll
        for (int cc = 0; cc < 16; cc++) {
            float4 a0 = *reinterpret_cast<const float4*>(&Xs[cc][ty * 8]);
            float4 a1 = *reinterpret_cast<const float4*>(&Xs[cc][ty * 8 + 4]);
            float4 bv = *reinterpret_cast<const float4*>(&Ws[cc][tx * 4]);
            float aa[8] = {a0.x, a0.y, a0.z, a0.w, a1.x, a1.y, a1.z, a1.w};
            float bb[4] = {bv.x, bv.y, bv.z, bv.w};
#pragma unroll
            for (int r = 0; r < 8; r++)
#pragma unroll
                for (int u = 0; u < 4; u++) acc[r][u] += aa[r] * bb[u];
        }
        __syncthreads();
    }

    if (o0 + tx * 4 < O) {
        float4 bs = *reinterpret_cast<const float4*>(bias + o0 + tx * 4);
        float bb[4] = {bs.x, bs.y, bs.z, bs.w};
        if (sel == 2) {
#pragma unroll
            for (int r = 0; r < 8; r++) {
                float4 v = make_float4(acc[r][0] + bb[0], acc[r][1] + bb[1],
                                       acc[r][2] + bb[2], acc[r][3] + bb[3]);
                *reinterpret_cast<float4*>(g_V + ((size_t)b * NDIM + i0 + ty * 8 + r) * O + o0 + tx * 4) = v;
            }
        } else {
            float* Oh = (sel == 0) ? g_Qh : g_Kh;
            float* Ol = (sel == 0) ? g_Ql : g_Kl;
#pragma unroll
            for (int r = 0; r < 8; r++) {
                const size_t row = ((size_t)b * NDIM + i0 + ty * 8 + r) * 32;
#pragma unroll
                for (int u = 0; u < 4; u++) {
                    float v = acc[r][u] + bb[u];
                    float hf = __uint_as_float(f2tf(v));
                    float lf = __uint_as_float(f2tf(v - hf));
                    int pos = kperm(tx * 4 + u);   // o0 == 0 for O=32
                    Oh[row + pos] = hf;
                    Ol[row + pos] = lf;
                }
            }
        }
    }
}

// =============================================================================
// Transpose V: g_V[b][j][c] -> g_V2[b][c][perm(j)], tf32-rounded
// =============================================================================
__global__ __launch_bounds__(256) void transpose_v_kernel()
{
    __shared__ float ts[32][33];
    const int j0 = blockIdx.x * 32;
    const int c0 = blockIdx.y * 32;
    const int b  = blockIdx.z;
    const int tx = threadIdx.x;
    const int ty = threadIdx.y;
#pragma unroll
    for (int k = 0; k < 4; k++)
        ts[ty + 8 * k][tx] = g_V[((size_t)b * NDIM + j0 + ty + 8 * k) * CDIM + c0 + tx];
    __syncthreads();
    const int jp = j0 + kperm(tx);
#pragma unroll
    for (int k = 0; k < 4; k++)
        g_V2[((size_t)b * CDIM + c0 + ty + 8 * k) * NDIM + jp] =
            __uint_as_float(f2tf(ts[tx][ty + 8 * k]));
}

// =============================================================================
// tf32 mma.sync flash attention, 2 CTAs/SM (114.9 KB smem), single wave.
// Single-buffered K/V with SPLIT WAITS (the R9 fix):
//   loop top:      wait_group 1  -> K(tl) ready (V(tl) may still fly)
//   after B2:      fillK(tl+1)   -> overlaps exp+PV
//   after exp:     wait_group 1  -> V(tl) ready (K(tl+1) may still fly)
//   after PV (B0): fillV(tl+1)   -> overlaps next QK+exp
// smem floats: Qh/Ql 2x2048 | Kh/Kl 2x2048 | V 256x64 | S 64x64 | den 64
// =============================================================================
#define QH_OFF  0
#define QL_OFF  2048
#define KH_OFF  4096
#define KL_OFF  6144
#define V_OFF   8192
#define S_OFF   24576
#define DEN_OFF 28672
#define SMEM_FLOATS 28736
#define SMEM_ATTN (SMEM_FLOATS * 4)   // 114944 B

__global__ __launch_bounds__(256, 2) void attn_kernel(
    const float* __restrict__ x, const float* __restrict__ gamma,
    float* __restrict__ out)
{
    extern __shared__ float smf[];
    const uint32_t sb = smem_u32(smf);
    const int t  = threadIdx.x;
    const int w  = t >> 5;
    const int lg = (t & 31) >> 2;
    const int l4 = t & 3;
    const int b  = blockIdx.y;
    const int i0 = blockIdx.x * 64;

    // ---- Q preload (split+interleaved in gmem) into swizzled smem ----
#pragma unroll
    for (int it = 0; it < 2; it++) {
        int idx = it * 256 + t;           // 512 16B-chunks per part
        int r = idx >> 3, q = idx & 7;
        const size_t gsrc = ((size_t)(b * NDIM + i0 + r) << 5) + q * 4;
        const int dc = SWZ(r, q * 4);
        *reinterpret_cast<float4*>(&smf[QH_OFF + r * 32 + dc]) =
            *reinterpret_cast<const float4*>(g_Qh + gsrc);
        *reinterpret_cast<float4*>(&smf[QL_OFF + r * 32 + dc]) =
            *reinterpret_cast<const float4*>(g_Ql + gsrc);
    }

    auto fillK = [&](int tl) {
        const int j0 = tl << 6;
#pragma unroll
        for (int it = 0; it < 2; it++) {
            int idx = it * 256 + t;
            int r = idx >> 3, q = idx & 7;
            const size_t gsrc = ((size_t)(b * NDIM + j0 + r) << 5) + q * 4;
            const int dc = SWZ(r, q * 4);
            cpa16(sb + (KH_OFF + r * 32 + dc) * 4, g_Kh + gsrc);
            cpa16(sb + (KL_OFF + r * 32 + dc) * 4, g_Kl + gsrc);
        }
        CP_COMMIT();
    };
    auto fillV = [&](int tl) {
        const int j0 = tl << 6;
#pragma unroll
        for (int it = 0; it < 16; it++) {
            int idx = it * 256 + t;
            int cr = idx >> 4, q = idx & 15;
            cpa16(sb + (V_OFF + cr * 64 + SWZ(cr, q * 4)) * 4,
                  g_V2 + ((size_t)(b * CDIM + cr) << 12) + j0 + q * 4);
        }
        CP_COMMIT();
    };

    fillK(0);   // group: K(0)
    fillV(0);   // group: V(0)

    // PV: warp tile rows pm0..+31, cols pn0..+63
    const int pm0 = (w & 1) * 32;
    const int pn0 = (w >> 1) * 64;
    float acc[2][8][4];
#pragma unroll
    for (int mt = 0; mt < 2; mt++)
#pragma unroll
        for (int nt = 0; nt < 8; nt++)
#pragma unroll
            for (int u = 0; u < 4; u++) acc[mt][nt][u] = 0.f;

    // QK: warp tile rows qm0..+15, cols qn0..+31
    const int qm0 = (w & 3) * 16;
    const int qn0 = (w >> 2) * 32;

    // softmax ownership: thread owns row sr, cols sc..sc+15
    const int sr = t >> 2;
    const int sc = (t & 3) * 16;
    float den = 0.f;

    for (int tl = 0; tl < 64; tl++) {
        // K(tl) is the older of the <=2 pending groups; V(tl) may stay in flight
        CP_WAIT1();
        __syncthreads();                         // B1: K(tl) (and Q) visible

        // ---- S = Q.K^T, 3-term tf32 split ----
        {
            float sfrag[4][4];
#pragma unroll
            for (int nt = 0; nt < 4; nt++)
#pragma unroll
                for (int u = 0; u < 4; u++) sfrag[nt][u] = 0.f;

#pragma unroll
            for (int kst = 0; kst < 4; kst++) {
                const int k0 = kst * 8 + 2 * l4;
                const int asw = SWZ(lg, k0);
                uint2 ah0 = *reinterpret_cast<const uint2*>(&smf[QH_OFF + (qm0 + lg)     * 32 + asw]);
                uint2 ah1 = *reinterpret_cast<const uint2*>(&smf[QH_OFF + (qm0 + lg + 8) * 32 + asw]);
                uint2 al0 = *reinterpret_cast<const uint2*>(&smf[QL_OFF + (qm0 + lg)     * 32 + asw]);
                uint2 al1 = *reinterpret_cast<const uint2*>(&smf[QL_OFF + (qm0 + lg + 8) * 32 + asw]);
#pragma unroll
                for (int nt = 0; nt < 4; nt++) {
                    const int jr = qn0 + nt * 8 + lg;
                    uint2 bh = *reinterpret_cast<const uint2*>(&smf[KH_OFF + jr * 32 + asw]);
                    uint2 bl = *reinterpret_cast<const uint2*>(&smf[KL_OFF + jr * 32 + asw]);
                    mma_tf32(sfrag[nt], ah0.x, ah1.x, ah0.y, ah1.y, bh.x, bh.y);
                    mma_tf32(sfrag[nt], ah0.x, ah1.x, ah0.y, ah1.y, bl.x, bl.y);
                    mma_tf32(sfrag[nt], al0.x, al1.x, al0.y, al1.y, bh.x, bh.y);
                }
            }
#pragma unroll
            for (int nt = 0; nt < 4; nt++) {
                const int col = qn0 + nt * 8 + 2 * l4;
                *reinterpret_cast<float2*>(&smf[S_OFF + (qm0 + lg) * 64 + SWZ(lg, col)]) =
                    make_float2(sfrag[nt][0], sfrag[nt][1]);
                *reinterpret_cast<float2*>(&smf[S_OFF + (qm0 + lg + 8) * 64 + SWZ(lg, col)]) =
                    make_float2(sfrag[nt][2], sfrag[nt][3]);
            }
        }
        __syncthreads();                         // B2: S done, K buffer dead
        if (tl < 63) fillK(tl + 1);              // group K(tl+1): overlaps exp+PV

        // ---- P = tf32(exp(S)) written k-interleaved; den += rowsum ----
        {
            float p[16];
            float rsum = 0.f;
#pragma unroll
            for (int i = 0; i < 4; i++) {
                float4 v = *reinterpret_cast<const float4*>(
                    &smf[S_OFF + sr * 64 + SWZ(sr, sc + 4 * i)]);
                p[4*i+0] = __uint_as_float(f2tf(__expf(v.x)));
                p[4*i+1] = __uint_as_float(f2tf(__expf(v.y)));
                p[4*i+2] = __uint_as_float(f2tf(__expf(v.z)));
                p[4*i+3] = __uint_as_float(f2tf(__expf(v.w)));
                rsum += p[4*i+0] + p[4*i+1] + p[4*i+2] + p[4*i+3];
            }
            rsum += __shfl_xor_sync(0xffffffffu, rsum, 1);
            rsum += __shfl_xor_sync(0xffffffffu, rsum, 2);
            den += rsum;
#pragma unroll
            for (int c2 = 0; c2 < 2; c2++)
#pragma unroll
                for (int j = 0; j < 4; j++)
                    *reinterpret_cast<float2*>(
                        &smf[S_OFF + sr * 64 + SWZ(sr, sc + c2 * 8 + 2 * j)]) =
                        make_float2(p[c2 * 8 + j], p[c2 * 8 + j + 4]);
        }
        // V(tl) is the older pending group (K(tl+1) newer); retire it now.
        if (tl < 63) CP_WAIT1(); else CP_WAIT0();
        __syncthreads();                         // B3: P stores + V(tl) visible

        // ---- OUT += P.V ----
        {
#pragma unroll
            for (int kst = 0; kst < 8; kst++) {
                const int k0 = kst * 8 + 2 * l4;
                const int ksw = SWZ(lg, k0);
                uint2 pa[2][2];
#pragma unroll
                for (int mt = 0; mt < 2; mt++) {
                    const int r0 = pm0 + mt * 16;
                    pa[mt][0] = *reinterpret_cast<const uint2*>(&smf[S_OFF + (r0 + lg)     * 64 + ksw]);
                    pa[mt][1] = *reinterpret_cast<const uint2*>(&smf[S_OFF + (r0 + lg + 8) * 64 + ksw]);
                }
#pragma unroll
                for (int nt = 0; nt < 8; nt++) {
                    const int cr = pn0 + nt * 8 + lg;
                    uint2 bv = *reinterpret_cast<const uint2*>(&smf[V_OFF + cr * 64 + ksw]);
                    mma_tf32(acc[0][nt], pa[0][0].x, pa[0][1].x, pa[0][0].y, pa[0][1].y, bv.x, bv.y);
                    mma_tf32(acc[1][nt], pa[1][0].x, pa[1][1].x, pa[1][0].y, pa[1][1].y, bv.x, bv.y);
                }
            }
        }
        __syncthreads();                         // B0: PV done, V buffer dead
        if (tl < 63) fillV(tl + 1);              // group V(tl+1): overlaps next QK+exp
    }

    // ---- epilogue ----
    if ((t & 3) == 0) smf[DEN_OFF + sr] = den;
    __syncthreads();

    const float ga = gamma[0];
    const float* xb = x   + (size_t)b * CDIM * NDIM;
    float*       ob = out + (size_t)b * CDIM * NDIM;

#pragma unroll
    for (int mt = 0; mt < 2; mt++) {
        const int r0 = pm0 + mt * 16;
        const float inv0 = 1.f / smf[DEN_OFF + r0 + lg];
        const float inv1 = 1.f / smf[DEN_OFF + r0 + lg + 8];
        const int gi0 = i0 + r0 + lg;
#pragma unroll
        for (int nt = 0; nt < 8; nt++) {
            const int col = pn0 + nt * 8 + 2 * l4;
            const size_t b00 = (size_t)col * NDIM + gi0;
            const size_t b10 = b00 + NDIM;
            ob[b00]     = ga * (acc[mt][nt][0] * inv0) + xb[b00];
            ob[b10]     = ga * (acc[mt][nt][1] * inv0) + xb[b10];
            ob[b00 + 8] = ga * (acc[mt][nt][2] * inv1) + xb[b00 + 8];
            ob[b10 + 8] = ga * (acc[mt][nt][3] * inv1) + xb[b10 + 8];
        }
    }
}

// =============================================================================
extern "C" void kernel_launch(void* const* d_in, const int* in_sizes, int n_in,
                              void* d_out, int out_size)
{
    (void)in_sizes; (void)n_in; (void)out_size;
    const float* x     = (const float*)d_in[0];
    const float* Wq    = (const float*)d_in[1];
    const float* bq    = (const float*)d_in[2];
    const float* Wk    = (const float*)d_in[3];
    const float* bk    = (const float*)d_in[4];
    const float* Wv    = (const float*)d_in[5];
    const float* bv    = (const float*)d_in[6];
    const float* gamma = (const float*)d_in[7];
    float* out = (float*)d_out;

    (void)cudaFuncSetAttribute(attn_kernel,
                               cudaFuncAttributeMaxDynamicSharedMemorySize, SMEM_ATTN);

    dim3 gq(NDIM / 128, 1, BB);
    dim3 gv(NDIM / 128, 4, BB);
    proj_kernel<<<gq, 256>>>(x, Wq, bq, C8,   0);
    proj_kernel<<<gq, 256>>>(x, Wk, bk, C8,   1);
    proj_kernel<<<gv, 256>>>(x, Wv, bv, CDIM, 2);

    dim3 gt(NDIM / 32, CDIM / 32, BB);
    transpose_v_kernel<<<gt, dim3(32, 8)>>>();

    dim3 ga(NDIM / 64, BB);    // 256 CTAs, 2 per SM -> single wave
    attn_kernel<<<ga, 256, SMEM_ATTN>>>(x, gamma, out);
}

// round 12
// speedup vs baseline: 1.1281x; 1.1180x over previous
#include <cuda_runtime.h>
#include <math_constants.h>
#include <cstdint>

// Problem shape (fixed by setup_inputs): x[4,256,64,64]
#define BB   4
#define CDIM 256
#define NDIM 4096
#define C8   32

// ---------------- scratch (static device globals; no allocation) -------------
__device__ float g_Qh[BB * NDIM * C8];
__device__ float g_Ql[BB * NDIM * C8];
__device__ float g_Kh[BB * NDIM * C8];
__device__ float g_Kl[BB * NDIM * C8];
__device__ float g_V [BB * NDIM * CDIM];  // V[b][j][c] raw fp32
__device__ float g_V2[BB * CDIM * NDIM];  // V[b][c][j], tf32-rounded, j-interleaved

// =============================================================================
// helpers
// =============================================================================
__device__ __forceinline__ uint32_t smem_u32(const void* p) {
    uint32_t a;
    asm("{ .reg .u64 t; cvta.to.shared.u64 t, %1; cvt.u32.u64 %0, t; }" : "=r"(a) : "l"(p));
    return a;
}
__device__ __forceinline__ uint32_t f2tf(float x) {
    uint32_t r;
    asm("cvt.rna.tf32.f32 %0, %1;" : "=r"(r) : "f"(x));
    return r;
}
// interleave within 8-chunk: k -> 2*(k&3) + ((k&4)>>2)
__device__ __forceinline__ int kperm(int c) {
    return (c & ~7) + 2 * (c & 3) + ((c & 4) >> 2);
}
// smem swizzle: XOR float-col by 8*(row&3); fragment loads conflict-free
// (16-lane phases hold 4 distinct row&3 values -> distinct bank octets)
#define SWZ(r, c) ((c) ^ (8 * ((r) & 3)))

__device__ __forceinline__ void mma_tf32(float c[4], uint32_t a0, uint32_t a1,
                                         uint32_t a2, uint32_t a3,
                                         uint32_t b0, uint32_t b1) {
    asm volatile(
        "mma.sync.aligned.m16n8k8.row.col.f32.tf32.tf32.f32 "
        "{%0,%1,%2,%3}, {%4,%5,%6,%7}, {%8,%9}, {%0,%1,%2,%3};"
        : "+f"(c[0]), "+f"(c[1]), "+f"(c[2]), "+f"(c[3])
        : "r"(a0), "r"(a1), "r"(a2), "r"(a3), "r"(b0), "r"(b1));
}
__device__ __forceinline__ void cpa16(uint32_t dst, const void* src) {
    asm volatile("cp.async.cg.shared.global [%0], [%1], 16;" :: "r"(dst), "l"(src) : "memory");
}
#define CP_COMMIT() asm volatile("cp.async.commit_group;" ::: "memory")
#define CP_WAIT1()  asm volatile("cp.async.wait_group 1;" ::: "memory")
#define CP_WAIT0()  asm volatile("cp.async.wait_group 0;" ::: "memory")

// =============================================================================
// Projection. sel 0/1 (Q/K, O=32): write tf32 high/low split, k-interleaved.
// sel 2 (V, O=256): raw float4 to g_V.    (unchanged, passing since R7)
// =============================================================================
__global__ __launch_bounds__(256) void proj_kernel(
    const float* __restrict__ x, const float* __restrict__ Wm,
    const float* __restrict__ bias, int O, int sel)
{
    __shared__ float Xs[16][128];
    __shared__ float Ws[16][64];

    const int b  = blockIdx.z;
    const int i0 = blockIdx.x * 128;
    const int o0 = blockIdx.y * 64;
    const int t  = threadIdx.x;
    const int tx = t & 15;
    const int ty = t >> 4;

    const float* xb = x + (size_t)b * CDIM * NDIM;

    float acc[8][4];
#pragma unroll
    for (int r = 0; r < 8; r++)
#pragma unroll
        for (int u = 0; u < 4; u++) acc[r][u] = 0.f;

    for (int c0 = 0; c0 < CDIM; c0 += 16) {
#pragma unroll
        for (int l = t; l < 512; l += 256) {
            int r = l >> 5, q = l & 31;
            float4 v = *reinterpret_cast<const float4*>(xb + (size_t)(c0 + r) * NDIM + i0 + q * 4);
            *reinterpret_cast<float4*>(&Xs[r][q * 4]) = v;
        }
        {
            int o = t >> 2, c4 = (t & 3) * 4;
            float4 w = make_float4(0.f, 0.f, 0.f, 0.f);
            if (o0 + o < O)
                w = *reinterpret_cast<const float4*>(Wm + (size_t)(o0 + o) * CDIM + c0 + c4);
            Ws[c4 + 0][o] = w.x; Ws[c4 + 1][o] = w.y;
            Ws[c4 + 2][o] = w.z; Ws[c4 + 3][o] = w.w;
        }
        __syncthreads();
#pragma unroll
        for (int cc = 0; cc < 16; cc++) {
            float4 a0 = *reinterpret_cast<const float4*>(&Xs[cc][ty * 8]);
            float4 a1 = *reinterpret_cast<const float4*>(&Xs[cc][ty * 8 + 4]);
            float4 bv = *reinterpret_cast<const float4*>(&Ws[cc][tx * 4]);
            float aa[8] = {a0.x, a0.y, a0.z, a0.w, a1.x, a1.y, a1.z, a1.w};
            float bb[4] = {bv.x, bv.y, bv.z, bv.w};
#pragma unroll
            for (int r = 0; r < 8; r++)
#pragma unroll
                for (int u = 0; u < 4; u++) acc[r][u] += aa[r] * bb[u];
        }
        __syncthreads();
    }

    if (o0 + tx * 4 < O) {
        float4 bs = *reinterpret_cast<const float4*>(bias + o0 + tx * 4);
        float bb[4] = {bs.x, bs.y, bs.z, bs.w};
        if (sel == 2) {
#pragma unroll
            for (int r = 0; r < 8; r++) {
                float4 v = make_float4(acc[r][0] + bb[0], acc[r][1] + bb[1],
                                       acc[r][2] + bb[2], acc[r][3] + bb[3]);
                *reinterpret_cast<float4*>(g_V + ((size_t)b * NDIM + i0 + ty * 8 + r) * O + o0 + tx * 4) = v;
            }
        } else {
            float* Oh = (sel == 0) ? g_Qh : g_Kh;
            float* Ol = (sel == 0) ? g_Ql : g_Kl;
#pragma unroll
            for (int r = 0; r < 8; r++) {
                const size_t row = ((size_t)b * NDIM + i0 + ty * 8 + r) * 32;
#pragma unroll
                for (int u = 0; u < 4; u++) {
                    float v = acc[r][u] + bb[u];
                    float hf = __uint_as_float(f2tf(v));
                    float lf = __uint_as_float(f2tf(v - hf));
                    int pos = kperm(tx * 4 + u);   // o0 == 0 for O=32
                    Oh[row + pos] = hf;
                    Ol[row + pos] = lf;
                }
            }
        }
    }
}

// =============================================================================
// Transpose V: g_V[b][j][c] -> g_V2[b][c][perm(j)], tf32-rounded  (unchanged)
// =============================================================================
__global__ __launch_bounds__(256) void transpose_v_kernel()
{
    __shared__ float ts[32][33];
    const int j0 = blockIdx.x * 32;
    const int c0 = blockIdx.y * 32;
    const int b  = blockIdx.z;
    const int tx = threadIdx.x;
    const int ty = threadIdx.y;
#pragma unroll
    for (int k = 0; k < 4; k++)
        ts[ty + 8 * k][tx] = g_V[((size_t)b * NDIM + j0 + ty + 8 * k) * CDIM + c0 + tx];
    __syncthreads();
    const int jp = j0 + kperm(tx);
#pragma unroll
    for (int k = 0; k < 4; k++)
        g_V2[((size_t)b * CDIM + c0 + ty + 8 * k) * NDIM + jp] =
            __uint_as_float(f2tf(ts[tx][ty + 8 * k]));
}

// =============================================================================
// tf32 mma.sync flash attention, 128-QUERY CTAs: bigger warp tiles cut smem
// fragment traffic per q·k by ~29% and halve per-work loop overhead.
// CTA = 128 queries x 256 threads, 64-key tiles, double-buffered K/V (R8
// schedule). 128 CTAs -> single wave. Numerics identical to R8/R10.
// smem floats: Qh/Ql 2x4096 | K 2x(2048h+2048l) | V 2x16384 | S 128x64 | den
// = 57,472 fl = 229,888 B (occ 1; fits 227KB opt-in cap)
// =============================================================================
#define QH_OFF  0
#define QL_OFF  4096
#define K_OFF   8192
#define KBUF    4096     // per buffer: h(2048) + l(2048)
#define V_OFF   16384
#define VBUF    16384    // 256 x 64
#define S_OFF   49152    // 128 x 64
#define DEN_OFF 57344
#define SMEM_FLOATS 57472
#define SMEM_ATTN (SMEM_FLOATS * 4)   // 229888 B

__global__ __launch_bounds__(256, 1) void attn_kernel(
    const float* __restrict__ x, const float* __restrict__ gamma,
    float* __restrict__ out)
{
    extern __shared__ float smf[];
    const uint32_t sb = smem_u32(smf);
    const int t  = threadIdx.x;
    const int w  = t >> 5;
    const int lg = (t & 31) >> 2;
    const int l4 = t & 3;
    const int b  = blockIdx.y;
    const int i0 = blockIdx.x * 128;

    // ---- Q preload: 128 rows x 32 d, h+l, swizzled ----
#pragma unroll
    for (int it = 0; it < 4; it++) {
        int idx = it * 256 + t;           // 1024 16B-chunks per part
        int r = idx >> 3, q = idx & 7;
        const size_t gsrc = ((size_t)(b * NDIM + i0 + r) << 5) + q * 4;
        const int dc = SWZ(r, q * 4);
        *reinterpret_cast<float4*>(&smf[QH_OFF + r * 32 + dc]) =
            *reinterpret_cast<const float4*>(g_Qh + gsrc);
        *reinterpret_cast<float4*>(&smf[QL_OFF + r * 32 + dc]) =
            *reinterpret_cast<const float4*>(g_Ql + gsrc);
    }

    auto fill = [&](int tl, int buf) {
        const int j0 = tl << 6;
        const uint32_t kh = sb + (K_OFF + buf * KBUF) * 4;
        const uint32_t kl = kh + 2048 * 4;
        const uint32_t vb = sb + (V_OFF + buf * VBUF) * 4;
#pragma unroll
        for (int it = 0; it < 2; it++) {   // K h+l: 64 rows x 32 d
            int idx = it * 256 + t;
            int r = idx >> 3, q = idx & 7;
            const size_t gsrc = ((size_t)(b * NDIM + j0 + r) << 5) + q * 4;
            const int dc = SWZ(r, q * 4);
            cpa16(kh + (r * 32 + dc) * 4, g_Kh + gsrc);
            cpa16(kl + (r * 32 + dc) * 4, g_Kl + gsrc);
        }
#pragma unroll
        for (int it = 0; it < 16; it++) {  // V2: 256 c-rows x 64 j
            int idx = it * 256 + t;
            int cr = idx >> 4, q = idx & 15;
            cpa16(vb + (cr * 64 + SWZ(cr, q * 4)) * 4,
                  g_V2 + ((size_t)(b * CDIM + cr) << 12) + j0 + q * 4);
        }
        CP_COMMIT();
    };

    fill(0, 0);

    // PV: warp tile rows pm0..+63, cols pn0..+63
    const int pm0 = (w & 1) * 64;
    const int pn0 = (w >> 1) * 64;
    float acc[4][8][4];
#pragma unroll
    for (int mt = 0; mt < 4; mt++)
#pragma unroll
        for (int nt = 0; nt < 8; nt++)
#pragma unroll
            for (int u = 0; u < 4; u++) acc[mt][nt][u] = 0.f;

    // QK: warp tile rows qm0..+31, cols qn0..+31
    const int qm0 = (w & 3) * 32;
    const int qn0 = (w >> 2) * 32;

    // softmax ownership: thread owns row sr, cols sc..sc+31
    const int sr = t >> 1;
    const int sc = (t & 1) * 32;
    float den = 0.f;

    for (int tl = 0; tl < 64; tl++) {
        const int buf = tl & 1;
        __syncthreads();                         // B0: PV(tl-1) reads done
        if (tl < 63) { fill(tl + 1, buf ^ 1); CP_WAIT1(); }
        else         { CP_WAIT0(); }
        __syncthreads();                         // B1: tile tl K/V (and Q) visible

        // ---- S = Q.K^T, 3-term tf32 split (M=128 N=64 per CTA) ----
        {
            const int khb = K_OFF + buf * KBUF;
            const int klb = khb + 2048;
            float sfrag[2][4][4];
#pragma unroll
            for (int mt = 0; mt < 2; mt++)
#pragma unroll
                for (int nt = 0; nt < 4; nt++)
#pragma unroll
                    for (int u = 0; u < 4; u++) sfrag[mt][nt][u] = 0.f;

#pragma unroll
            for (int kst = 0; kst < 4; kst++) {
                const int k0 = kst * 8 + 2 * l4;
                const int asw = SWZ(lg, k0);
                uint2 ah[2][2], al[2][2];
#pragma unroll
                for (int mt = 0; mt < 2; mt++) {
                    const int r0 = qm0 + mt * 16;
                    ah[mt][0] = *reinterpret_cast<const uint2*>(&smf[QH_OFF + (r0 + lg)     * 32 + asw]);
                    ah[mt][1] = *reinterpret_cast<const uint2*>(&smf[QH_OFF + (r0 + lg + 8) * 32 + asw]);
                    al[mt][0] = *reinterpret_cast<const uint2*>(&smf[QL_OFF + (r0 + lg)     * 32 + asw]);
                    al[mt][1] = *reinterpret_cast<const uint2*>(&smf[QL_OFF + (r0 + lg + 8) * 32 + asw]);
                }
#pragma unroll
                for (int nt = 0; nt < 4; nt++) {
                    const int jr = qn0 + nt * 8 + lg;
                    uint2 bh = *reinterpret_cast<const uint2*>(&smf[khb + jr * 32 + asw]);
                    uint2 bl = *reinterpret_cast<const uint2*>(&smf[klb + jr * 32 + asw]);
#pragma unroll
                    for (int mt = 0; mt < 2; mt++) {
                        mma_tf32(sfrag[mt][nt], ah[mt][0].x, ah[mt][1].x, ah[mt][0].y, ah[mt][1].y, bh.x, bh.y);
                        mma_tf32(sfrag[mt][nt], ah[mt][0].x, ah[mt][1].x, ah[mt][0].y, ah[mt][1].y, bl.x, bl.y);
                        mma_tf32(sfrag[mt][nt], al[mt][0].x, al[mt][1].x, al[mt][0].y, al[mt][1].y, bh.x, bh.y);
                    }
                }
            }
#pragma unroll
            for (int mt = 0; mt < 2; mt++) {
                const int r0 = qm0 + mt * 16;
#pragma unroll
                for (int nt = 0; nt < 4; nt++) {
                    const int col = qn0 + nt * 8 + 2 * l4;
                    *reinterpret_cast<float2*>(&smf[S_OFF + (r0 + lg) * 64 + SWZ(lg, col)]) =
                        make_float2(sfrag[mt][nt][0], sfrag[mt][nt][1]);
                    *reinterpret_cast<float2*>(&smf[S_OFF + (r0 + lg + 8) * 64 + SWZ(lg, col)]) =
                        make_float2(sfrag[mt][nt][2], sfrag[mt][nt][3]);
                }
            }
        }
        __syncthreads();                         // B2: S complete

        // ---- P = tf32(exp(S)) k-interleaved; den += rowsum (2 thr/row) ----
        {
            float p[32];
            float rsum = 0.f;
#pragma unroll
            for (int i = 0; i < 8; i++) {
                float4 v = *reinterpret_cast<const float4*>(
                    &smf[S_OFF + sr * 64 + SWZ(sr, sc + 4 * i)]);
                p[4*i+0] = __uint_as_float(f2tf(__expf(v.x)));
                p[4*i+1] = __uint_as_float(f2tf(__expf(v.y)));
                p[4*i+2] = __uint_as_float(f2tf(__expf(v.z)));
                p[4*i+3] = __uint_as_float(f2tf(__expf(v.w)));
                rsum += p[4*i+0] + p[4*i+1] + p[4*i+2] + p[4*i+3];
            }
            rsum += __shfl_xor_sync(0xffffffffu, rsum, 1);   // lane^1 = same row
            den += rsum;
#pragma unroll
            for (int c2 = 0; c2 < 4; c2++)
#pragma unroll
                for (int j = 0; j < 4; j++)
                    *reinterpret_cast<float2*>(
                        &smf[S_OFF + sr * 64 + SWZ(sr, sc + c2 * 8 + 2 * j)]) =
                        make_float2(p[c2 * 8 + j], p[c2 * 8 + j + 4]);
        }
        __syncthreads();                         // B3: P complete

        // ---- OUT += P.V  (M=128, N=256, K=64; warp 64x64) ----
        {
            const int vbb = V_OFF + buf * VBUF;
#pragma unroll
            for (int kst = 0; kst < 8; kst++) {
                const int k0 = kst * 8 + 2 * l4;
                const int ksw = SWZ(lg, k0);
                uint2 pa[4][2];
#pragma unroll
                for (int mt = 0; mt < 4; mt++) {
                    const int r0 = pm0 + mt * 16;
                    pa[mt][0] = *reinterpret_cast<const uint2*>(&smf[S_OFF + (r0 + lg)     * 64 + ksw]);
                    pa[mt][1] = *reinterpret_cast<const uint2*>(&smf[S_OFF + (r0 + lg + 8) * 64 + ksw]);
                }
#pragma unroll
                for (int nt = 0; nt < 8; nt++) {
                    const int cr = pn0 + nt * 8 + lg;
                    uint2 bv = *reinterpret_cast<const uint2*>(&smf[vbb + cr * 64 + ksw]);
#pragma unroll
                    for (int mt = 0; mt < 4; mt++)
                        mma_tf32(acc[mt][nt], pa[mt][0].x, pa[mt][1].x,
                                 pa[mt][0].y, pa[mt][1].y, bv.x, bv.y);
                }
            }
        }
    }

    // ---- epilogue ----
    if ((t & 1) == 0) smf[DEN_OFF + sr] = den;
    __syncthreads();

    const float ga = gamma[0];
    const float* xb = x   + (size_t)b * CDIM * NDIM;
    float*       ob = out + (size_t)b * CDIM * NDIM;

#pragma unroll
    for (int mt = 0; mt < 4; mt++) {
        const int r0 = pm0 + mt * 16;
        const float inv0 = 1.f / smf[DEN_OFF + r0 + lg];
        const float inv1 = 1.f / smf[DEN_OFF + r0 + lg + 8];
        const int gi0 = i0 + r0 + lg;
#pragma unroll
        for (int nt = 0; nt < 8; nt++) {
            const int col = pn0 + nt * 8 + 2 * l4;
            const size_t b00 = (size_t)col * NDIM + gi0;
            const size_t b10 = b00 + NDIM;
            ob[b00]     = ga * (acc[mt][nt][0] * inv0) + xb[b00];
            ob[b10]     = ga * (acc[mt][nt][1] * inv0) + xb[b10];
            ob[b00 + 8] = ga * (acc[mt][nt][2] * inv1) + xb[b00 + 8];
            ob[b10 + 8] = ga * (acc[mt][nt][3] * inv1) + xb[b10 + 8];
        }
    }
}

// =============================================================================
extern "C" void kernel_launch(void* const* d_in, const int* in_sizes, int n_in,
                              void* d_out, int out_size)
{
    (void)in_sizes; (void)n_in; (void)out_size;
    const float* x     = (const float*)d_in[0];
    const float* Wq    = (const float*)d_in[1];
    const float* bq    = (const float*)d_in[2];
    const float* Wk    = (const float*)d_in[3];
    const float* bk    = (const float*)d_in[4];
    const float* Wv    = (const float*)d_in[5];
    const float* bv    = (const float*)d_in[6];
    const float* gamma = (const float*)d_in[7];
    float* out = (float*)d_out;

    (void)cudaFuncSetAttribute(attn_kernel,
                               cudaFuncAttributeMaxDynamicSharedMemorySize, SMEM_ATTN);

    dim3 gq(NDIM / 128, 1, BB);
    dim3 gv(NDIM / 128, 4, BB);
    proj_kernel<<<gq, 256>>>(x, Wq, bq, C8,   0);
    proj_kernel<<<gq, 256>>>(x, Wk, bk, C8,   1);
    proj_kernel<<<gv, 256>>>(x, Wv, bv, CDIM, 2);

    dim3 gt(NDIM / 32, CDIM / 32, BB);
    transpose_v_kernel<<<gt, dim3(32, 8)>>>();

    dim3 ga(NDIM / 128, BB);    // 128 CTAs, occ 1 -> single wave
    attn_kernel<<<ga, 256, SMEM_ATTN>>>(x, gamma, out);
}

// round 13
// speedup vs baseline: 1.2167x; 1.0786x over previous
#include <cuda_runtime.h>
#include <cuda_bf16.h>
#include <math_constants.h>
#include <cstdint>

// Problem shape (fixed by setup_inputs): x[4,256,64,64]
#define BB   4
#define CDIM 256
#define NDIM 4096
#define C8   32

// ---------------- scratch (static device globals; no allocation) -------------
// Q/K stored pre-split into bf16 high/low parts, pair-interleaved (kperm_bf).
__device__ __nv_bfloat16 g_Qh[BB * NDIM * C8];
__device__ __nv_bfloat16 g_Ql[BB * NDIM * C8];
__device__ __nv_bfloat16 g_Kh[BB * NDIM * C8];
__device__ __nv_bfloat16 g_Kl[BB * NDIM * C8];
__device__ float g_V [BB * NDIM * CDIM];  // V[b][j][c] raw fp32
__device__ float g_V2[BB * CDIM * NDIM];  // V[b][c][j], tf32-rounded, j-interleaved

// =============================================================================
// helpers
// =============================================================================
__device__ __forceinline__ uint32_t smem_u32(const void* p) {
    uint32_t a;
    asm("{ .reg .u64 t; cvta.to.shared.u64 t, %1; cvt.u32.u64 %0, t; }" : "=r"(a) : "l"(p));
    return a;
}
__device__ __forceinline__ uint32_t f2tf(float x) {
    uint32_t r;
    asm("cvt.rna.tf32.f32 %0, %1;" : "=r"(r) : "f"(x));
    return r;
}
// tf32 k8 interleave (V/j path): k -> 2*(k&3) + ((k&4)>>2) within 8-blocks
__device__ __forceinline__ int kperm(int c) {
    return (c & ~7) + 2 * (c & 3) + ((c & 4) >> 2);
}
// bf16 k16 pair interleave: pairs ordered p0,p4,p1,p5,p2,p6,p3,p7 per 16-block
// -> thread l4's chunk [4*l4..4*l4+3] = halves {2l4,2l4+1, 2l4+8,2l4+9}
__device__ __forceinline__ int kperm_bf(int k) {
    return (k & 16) + ((k >> 1) & 3) * 4 + ((k >> 3) & 1) * 2 + (k & 1);
}
// float-array swizzle (S/V tiles): XOR float-col by 8*(row&3)
#define SWZ(r, c) ((c) ^ (8 * ((r) & 3)))

__device__ __forceinline__ void mma_tf32(float c[4], uint32_t a0, uint32_t a1,
                                         uint32_t a2, uint32_t a3,
                                         uint32_t b0, uint32_t b1) {
    asm volatile(
        "mma.sync.aligned.m16n8k8.row.col.f32.tf32.tf32.f32 "
        "{%0,%1,%2,%3}, {%4,%5,%6,%7}, {%8,%9}, {%0,%1,%2,%3};"
        : "+f"(c[0]), "+f"(c[1]), "+f"(c[2]), "+f"(c[3])
        : "r"(a0), "r"(a1), "r"(a2), "r"(a3), "r"(b0), "r"(b1));
}
__device__ __forceinline__ void mma_bf16(float c[4], uint32_t a0, uint32_t a1,
                                         uint32_t a2, uint32_t a3,
                                         uint32_t b0, uint32_t b1) {
    asm volatile(
        "mma.sync.aligned.m16n8k16.row.col.f32.bf16.bf16.f32 "
        "{%0,%1,%2,%3}, {%4,%5,%6,%7}, {%8,%9}, {%0,%1,%2,%3};"
        : "+f"(c[0]), "+f"(c[1]), "+f"(c[2]), "+f"(c[3])
        : "r"(a0), "r"(a1), "r"(a2), "r"(a3), "r"(b0), "r"(b1));
}
__device__ __forceinline__ void cpa16(uint32_t dst, const void* src) {
    asm volatile("cp.async.cg.shared.global [%0], [%1], 16;" :: "r"(dst), "l"(src) : "memory");
}
#define CP_COMMIT() asm volatile("cp.async.commit_group;" ::: "memory")
#define CP_WAIT1()  asm volatile("cp.async.wait_group 1;" ::: "memory")
#define CP_WAIT0()  asm volatile("cp.async.wait_group 0;" ::: "memory")

// =============================================================================
// Projection. sel 0/1 (Q/K, O=32): write bf16 high/low split, kperm_bf layout.
// sel 2 (V, O=256): raw float4 to g_V.
// =============================================================================
__global__ __launch_bounds__(256) void proj_kernel(
    const float* __restrict__ x, const float* __restrict__ Wm,
    const float* __restrict__ bias, int O, int sel)
{
    __shared__ float Xs[16][128];
    __shared__ float Ws[16][64];

    const int b  = blockIdx.z;
    const int i0 = blockIdx.x * 128;
    const int o0 = blockIdx.y * 64;
    const int t  = threadIdx.x;
    const int tx = t & 15;
    const int ty = t >> 4;

    const float* xb = x + (size_t)b * CDIM * NDIM;

    float acc[8][4];
#pragma unroll
    for (int r = 0; r < 8; r++)
#pragma unroll
        for (int u = 0; u < 4; u++) acc[r][u] = 0.f;

    for (int c0 = 0; c0 < CDIM; c0 += 16) {
#pragma unroll
        for (int l = t; l < 512; l += 256) {
            int r = l >> 5, q = l & 31;
            float4 v = *reinterpret_cast<const float4*>(xb + (size_t)(c0 + r) * NDIM + i0 + q * 4);
            *reinterpret_cast<float4*>(&Xs[r][q * 4]) = v;
        }
        {
            int o = t >> 2, c4 = (t & 3) * 4;
            float4 w = make_float4(0.f, 0.f, 0.f, 0.f);
            if (o0 + o < O)
                w = *reinterpret_cast<const float4*>(Wm + (size_t)(o0 + o) * CDIM + c0 + c4);
            Ws[c4 + 0][o] = w.x; Ws[c4 + 1][o] = w.y;
            Ws[c4 + 2][o] = w.z; Ws[c4 + 3][o] = w.w;
        }
        __syncthreads();
#pragma unroll
        for (int cc = 0; cc < 16; cc++) {
            float4 a0 = *reinterpret_cast<const float4*>(&Xs[cc][ty * 8]);
            float4 a1 = *reinterpret_cast<const float4*>(&Xs[cc][ty * 8 + 4]);
            float4 bv = *reinterpret_cast<const float4*>(&Ws[cc][tx * 4]);
            float aa[8] = {a0.x, a0.y, a0.z, a0.w, a1.x, a1.y, a1.z, a1.w};
            float bb[4] = {bv.x, bv.y, bv.z, bv.w};
#pragma unroll
            for (int r = 0; r < 8; r++)
#pragma unroll
                for (int u = 0; u < 4; u++) acc[r][u] += aa[r] * bb[u];
        }
        __syncthreads();
    }

    if (o0 + tx * 4 < O) {
        float4 bs = *reinterpret_cast<const float4*>(bias + o0 + tx * 4);
        float bb[4] = {bs.x, bs.y, bs.z, bs.w};
        if (sel == 2) {
#pragma unroll
            for (int r = 0; r < 8; r++) {
                float4 v = make_float4(acc[r][0] + bb[0], acc[r][1] + bb[1],
                                       acc[r][2] + bb[2], acc[r][3] + bb[3]);
                *reinterpret_cast<float4*>(g_V + ((size_t)b * NDIM + i0 + ty * 8 + r) * O + o0 + tx * 4) = v;
            }
        } else {
            __nv_bfloat16* Oh = (sel == 0) ? g_Qh : g_Kh;
            __nv_bfloat16* Ol = (sel == 0) ? g_Ql : g_Kl;
#pragma unroll
            for (int r = 0; r < 8; r++) {
                const size_t row = ((size_t)b * NDIM + i0 + ty * 8 + r) * 32;
#pragma unroll
                for (int u = 0; u < 4; u++) {
                    float v = acc[r][u] + bb[u];
                    __nv_bfloat16 hb = __float2bfloat16(v);           // rn
                    __nv_bfloat16 lb = __float2bfloat16(v - __bfloat162float(hb));
                    int pos = kperm_bf(tx * 4 + u);   // o0 == 0 for O=32
                    Oh[row + pos] = hb;
                    Ol[row + pos] = lb;
                }
            }
        }
    }
}

// =============================================================================
// Transpose V: g_V[b][j][c] -> g_V2[b][c][perm(j)], tf32-rounded  (unchanged)
// =============================================================================
__global__ __launch_bounds__(256) void transpose_v_kernel()
{
    __shared__ float ts[32][33];
    const int j0 = blockIdx.x * 32;
    const int c0 = blockIdx.y * 32;
    const int b  = blockIdx.z;
    const int tx = threadIdx.x;
    const int ty = threadIdx.y;
#pragma unroll
    for (int k = 0; k < 4; k++)
        ts[ty + 8 * k][tx] = g_V[((size_t)b * NDIM + j0 + ty + 8 * k) * CDIM + c0 + tx];
    __syncthreads();
    const int jp = j0 + kperm(tx);
#pragma unroll
    for (int k = 0; k < 4; k++)
        g_V2[((size_t)b * CDIM + c0 + ty + 8 * k) * NDIM + jp] =
            __uint_as_float(f2tf(ts[tx][ty + 8 * k]));
}

// =============================================================================
// Flash attention: QK in bf16-split m16n8k16 (halved instr + frag bytes),
// PV in tf32 (precision). 128-query CTAs, 64-key tiles, double-buffered K/V.
// Byte layout:
//   QH 0..8191 | QL 8192..16383 | K bufs 16384..32767 (2 x (KH 4K + KL 4K))
//   V 32768..163839 (2 x 64K) | S 163840..196607 | den 196608..197119
// Q/K rows: 64 B (32 bf16), 16B-chunk swizzle: chunk ^ (row&3).
// =============================================================================
#define QH_B    0
#define QL_B    8192
#define K_B     16384
#define KBUF_B  8192      // per buffer: KH 4096 + KL 4096
#define V_F     8192      // float index (byte 32768)
#define VBUF_F  16384     // 256 x 64 floats
#define S_F     40960     // float index (byte 163840), 128 x 64
#define DEN_F   49152     // float index (byte 196608)
#define SMEM_ATTN 197120

__global__ __launch_bounds__(256, 1) void attn_kernel(
    const float* __restrict__ x, const float* __restrict__ gamma,
    float* __restrict__ out)
{
    extern __shared__ float smf[];
    char* smc = reinterpret_cast<char*>(smf);
    const uint32_t sb = smem_u32(smf);
    const int t  = threadIdx.x;
    const int w  = t >> 5;
    const int lg = (t & 31) >> 2;
    const int l4 = t & 3;
    const int b  = blockIdx.y;
    const int i0 = blockIdx.x * 128;

    // ---- Q preload: 128 rows x 4 chunks x {h,l} = 1024 16B-chunks ----
#pragma unroll
    for (int it = 0; it < 4; it++) {
        int idx = it * 256 + t;
        int arr = idx >> 9;              // 0 = Qh, 1 = Ql
        int r   = (idx >> 2) & 127;
        int q   = idx & 3;
        const __nv_bfloat16* src = (arr ? g_Ql : g_Qh)
            + ((size_t)(b * NDIM + i0 + r) << 5) + q * 8;
        char* dst = smc + (arr ? QL_B : QH_B) + r * 64 + (q ^ (r & 3)) * 16;
        *reinterpret_cast<uint4*>(dst) = *reinterpret_cast<const uint4*>(src);
    }

    auto fill = [&](int tl, int buf) {
        const int j0 = tl << 6;
        const uint32_t kb = sb + K_B + buf * KBUF_B;
        const uint32_t vb = sb + V_F * 4 + buf * VBUF_F * 4;
        // K h+l: 64 rows x 4 chunks x 2 arrays = 512 chunks
#pragma unroll
        for (int it = 0; it < 2; it++) {
            int idx = it * 256 + t;
            int arr = idx >> 8;          // 0 = Kh, 1 = Kl
            int r   = (idx >> 2) & 63;
            int q   = idx & 3;
            const __nv_bfloat16* src = (arr ? g_Kl : g_Kh)
                + ((size_t)(b * NDIM + j0 + r) << 5) + q * 8;
            cpa16(kb + arr * 4096 + r * 64 + (q ^ (r & 3)) * 16, src);
        }
        // V2: 256 c-rows x 64 j
#pragma unroll
        for (int it = 0; it < 16; it++) {
            int idx = it * 256 + t;
            int cr = idx >> 4, q = idx & 15;
            cpa16(vb + (cr * 64 + SWZ(cr, q * 4)) * 4,
                  g_V2 + ((size_t)(b * CDIM + cr) << 12) + j0 + q * 4);
        }
        CP_COMMIT();
    };

    fill(0, 0);

    // PV: warp tile rows pm0..+63, cols pn0..+63
    const int pm0 = (w & 1) * 64;
    const int pn0 = (w >> 1) * 64;
    float acc[4][8][4];
#pragma unroll
    for (int mt = 0; mt < 4; mt++)
#pragma unroll
        for (int nt = 0; nt < 8; nt++)
#pragma unroll
            for (int u = 0; u < 4; u++) acc[mt][nt][u] = 0.f;

    // QK: warp tile rows qm0..+31, cols qn0..+31
    const int qm0 = (w & 3) * 32;
    const int qn0 = (w >> 2) * 32;

    // softmax ownership: thread owns row sr, cols sc..sc+31
    const int sr = t >> 1;
    const int sc = (t & 1) * 32;
    float den = 0.f;

    for (int tl = 0; tl < 64; tl++) {
        const int buf = tl & 1;
        __syncthreads();                         // B0: PV(tl-1) reads done
        if (tl < 63) { fill(tl + 1, buf ^ 1); CP_WAIT1(); }
        else         { CP_WAIT0(); }
        __syncthreads();                         // B1: tile tl K/V (and Q) visible

        // ---- S = Q.K^T, bf16 2-way-split 3-term, m16n8k16 (2 k-blocks) ----
        {
            const char* khb = smc + K_B + buf * KBUF_B;
            const char* klb = khb + 4096;
            float sfrag[2][4][4];
#pragma unroll
            for (int mt = 0; mt < 2; mt++)
#pragma unroll
                for (int nt = 0; nt < 4; nt++)
#pragma unroll
                    for (int u = 0; u < 4; u++) sfrag[mt][nt][u] = 0.f;

#pragma unroll
            for (int kst = 0; kst < 2; kst++) {
                const int co = 32 * kst + 8 * l4;      // chunk byte offset in row
                uint2 qh[2][2], ql[2][2];              // [mt][lo/hi row]
#pragma unroll
                for (int mt = 0; mt < 2; mt++) {
                    const int r0 = qm0 + mt * 16;
                    const int rA = r0 + lg, rB = r0 + lg + 8;
                    qh[mt][0] = *reinterpret_cast<const uint2*>(smc + QH_B + rA * 64 + (co ^ (16 * (rA & 3))));
                    qh[mt][1] = *reinterpret_cast<const uint2*>(smc + QH_B + rB * 64 + (co ^ (16 * (rB & 3))));
                    ql[mt][0] = *reinterpret_cast<const uint2*>(smc + QL_B + rA * 64 + (co ^ (16 * (rA & 3))));
                    ql[mt][1] = *reinterpret_cast<const uint2*>(smc + QL_B + rB * 64 + (co ^ (16 * (rB & 3))));
                }
#pragma unroll
                for (int nt = 0; nt < 4; nt++) {
                    const int jr = qn0 + nt * 8 + lg;
                    const int koff = jr * 64 + (co ^ (16 * (jr & 3)));
                    uint2 bh = *reinterpret_cast<const uint2*>(khb + koff);
                    uint2 bl = *reinterpret_cast<const uint2*>(klb + koff);
#pragma unroll
                    for (int mt = 0; mt < 2; mt++) {
                        mma_bf16(sfrag[mt][nt], qh[mt][0].x, qh[mt][1].x, qh[mt][0].y, qh[mt][1].y, bh.x, bh.y);
                        mma_bf16(sfrag[mt][nt], qh[mt][0].x, qh[mt][1].x, qh[mt][0].y, qh[mt][1].y, bl.x, bl.y);
                        mma_bf16(sfrag[mt][nt], ql[mt][0].x, ql[mt][1].x, ql[mt][0].y, ql[mt][1].y, bh.x, bh.y);
                    }
                }
            }
#pragma unroll
            for (int mt = 0; mt < 2; mt++) {
                const int r0 = qm0 + mt * 16;
#pragma unroll
                for (int nt = 0; nt < 4; nt++) {
                    const int col = qn0 + nt * 8 + 2 * l4;
                    *reinterpret_cast<float2*>(&smf[S_F + (r0 + lg) * 64 + SWZ(lg, col)]) =
                        make_float2(sfrag[mt][nt][0], sfrag[mt][nt][1]);
                    *reinterpret_cast<float2*>(&smf[S_F + (r0 + lg + 8) * 64 + SWZ(lg, col)]) =
                        make_float2(sfrag[mt][nt][2], sfrag[mt][nt][3]);
                }
            }
        }
        __syncthreads();                         // B2: S complete

        // ---- P = tf32(exp(S)) k-interleaved; den += rowsum (2 thr/row) ----
        {
            float p[32];
            float rsum = 0.f;
#pragma unroll
            for (int i = 0; i < 8; i++) {
                float4 v = *reinterpret_cast<const float4*>(
                    &smf[S_F + sr * 64 + SWZ(sr, sc + 4 * i)]);
                p[4*i+0] = __uint_as_float(f2tf(__expf(v.x)));
                p[4*i+1] = __uint_as_float(f2tf(__expf(v.y)));
                p[4*i+2] = __uint_as_float(f2tf(__expf(v.z)));
                p[4*i+3] = __uint_as_float(f2tf(__expf(v.w)));
                rsum += p[4*i+0] + p[4*i+1] + p[4*i+2] + p[4*i+3];
            }
            rsum += __shfl_xor_sync(0xffffffffu, rsum, 1);   // lane^1 = same row
            den += rsum;
#pragma unroll
            for (int c2 = 0; c2 < 4; c2++)
#pragma unroll
                for (int j = 0; j < 4; j++)
                    *reinterpret_cast<float2*>(
                        &smf[S_F + sr * 64 + SWZ(sr, sc + c2 * 8 + 2 * j)]) =
                        make_float2(p[c2 * 8 + j], p[c2 * 8 + j + 4]);
        }
        __syncthreads();                         // B3: P complete

        // ---- OUT += P.V  (tf32; M=128, N=256, K=64; warp 64x64) ----
        {
            const int vbb = V_F + buf * VBUF_F;
#pragma unroll
            for (int kst = 0; kst < 8; kst++) {
                const int k0 = kst * 8 + 2 * l4;
                const int ksw = SWZ(lg, k0);
                uint2 pa[4][2];
#pragma unroll
                for (int mt = 0; mt < 4; mt++) {
                    const int r0 = pm0 + mt * 16;
                    pa[mt][0] = *reinterpret_cast<const uint2*>(&smf[S_F + (r0 + lg)     * 64 + ksw]);
                    pa[mt][1] = *reinterpret_cast<const uint2*>(&smf[S_F + (r0 + lg + 8) * 64 + ksw]);
                }
#pragma unroll
                for (int nt = 0; nt < 8; nt++) {
                    const int cr = pn0 + nt * 8 + lg;
                    uint2 bv = *reinterpret_cast<const uint2*>(&smf[vbb + cr * 64 + ksw]);
#pragma unroll
                    for (int mt = 0; mt < 4; mt++)
                        mma_tf32(acc[mt][nt], pa[mt][0].x, pa[mt][1].x,
                                 pa[mt][0].y, pa[mt][1].y, bv.x, bv.y);
                }
            }
        }
    }

    // ---- epilogue ----
    if ((t & 1) == 0) smf[DEN_F + sr] = den;
    __syncthreads();

    const float ga = gamma[0];
    const float* xb = x   + (size_t)b * CDIM * NDIM;
    float*       ob = out + (size_t)b * CDIM * NDIM;

#pragma unroll
    for (int mt = 0; mt < 4; mt++) {
        const int r0 = pm0 + mt * 16;
        const float inv0 = 1.f / smf[DEN_F + r0 + lg];
        const float inv1 = 1.f / smf[DEN_F + r0 + lg + 8];
        const int gi0 = i0 + r0 + lg;
#pragma unroll
        for (int nt = 0; nt < 8; nt++) {
            const int col = pn0 + nt * 8 + 2 * l4;
            const size_t b00 = (size_t)col * NDIM + gi0;
            const size_t b10 = b00 + NDIM;
            ob[b00]     = ga * (acc[mt][nt][0] * inv0) + xb[b00];
            ob[b10]     = ga * (acc[mt][nt][1] * inv0) + xb[b10];
            ob[b00 + 8] = ga * (acc[mt][nt][2] * inv1) + xb[b00 + 8];
            ob[b10 + 8] = ga * (acc[mt][nt][3] * inv1) + xb[b10 + 8];
        }
    }
}

// =============================================================================
extern "C" void kernel_launch(void* const* d_in, const int* in_sizes, int n_in,
                              void* d_out, int out_size)
{
    (void)in_sizes; (void)n_in; (void)out_size;
    const float* x     = (const float*)d_in[0];
    const float* Wq    = (const float*)d_in[1];
    const float* bq    = (const float*)d_in[2];
    const float* Wk    = (const float*)d_in[3];
    const float* bk    = (const float*)d_in[4];
    const float* Wv    = (const float*)d_in[5];
    const float* bv    = (const float*)d_in[6];
    const float* gamma = (const float*)d_in[7];
    float* out = (float*)d_out;

    (void)cudaFuncSetAttribute(attn_kernel,
                               cudaFuncAttributeMaxDynamicSharedMemorySize, SMEM_ATTN);

    dim3 gq(NDIM / 128, 1, BB);
    dim3 gv(NDIM / 128, 4, BB);
    proj_kernel<<<gq, 256>>>(x, Wq, bq, C8,   0);
    proj_kernel<<<gq, 256>>>(x, Wk, bk, C8,   1);
    proj_kernel<<<gv, 256>>>(x, Wv, bv, CDIM, 2);

    dim3 gt(NDIM / 32, CDIM / 32, BB);
    transpose_v_kernel<<<gt, dim3(32, 8)>>>();

    dim3 ga(NDIM / 128, BB);    // 128 CTAs, occ 1 -> single wave
    attn_kernel<<<ga, 256, SMEM_ATTN>>>(x, gamma, out);
}

// round 15
// speedup vs baseline: 1.3174x; 1.0827x over previous
#include <cuda_runtime.h>
#include <cuda_bf16.h>
#include <math_constants.h>
#include <cstdint>

// Problem shape (fixed by setup_inputs): x[4,256,64,64]
#define BB   4
#define CDIM 256
#define NDIM 4096
#define C8   32

// ---------------- scratch (static device globals; no allocation) -------------
// Q/K stored pre-split into bf16 high/low parts, pair-interleaved (kperm_bf).
__device__ __nv_bfloat16 g_Qh[BB * NDIM * C8];
__device__ __nv_bfloat16 g_Ql[BB * NDIM * C8];
__device__ __nv_bfloat16 g_Kh[BB * NDIM * C8];
__device__ __nv_bfloat16 g_Kl[BB * NDIM * C8];
__device__ float g_V2[BB * CDIM * NDIM];  // V[b][c][j], tf32-rounded, j-interleaved

// =============================================================================
// helpers
// =============================================================================
__device__ __forceinline__ uint32_t smem_u32(const void* p) {
    uint32_t a;
    asm("{ .reg .u64 t; cvta.to.shared.u64 t, %1; cvt.u32.u64 %0, t; }" : "=r"(a) : "l"(p));
    return a;
}
__device__ __forceinline__ uint32_t f2tf(float x) {
    uint32_t r;
    asm("cvt.rna.tf32.f32 %0, %1;" : "=r"(r) : "f"(x));
    return r;
}
// bf16 k16 pair interleave for Q/K gmem layout
__device__ __forceinline__ int kperm_bf(int k) {
    return (k & 16) + ((k >> 1) & 3) * 4 + ((k >> 3) & 1) * 2 + (k & 1);
}
// float-array swizzle (S/V tiles): XOR float-col by 8*(row&3)
#define SWZ(r, c) ((c) ^ (8 * ((r) & 3)))

__device__ __forceinline__ void mma_tf32(float c[4], uint32_t a0, uint32_t a1,
                                         uint32_t a2, uint32_t a3,
                                         uint32_t b0, uint32_t b1) {
    asm volatile(
        "mma.sync.aligned.m16n8k8.row.col.f32.tf32.tf32.f32 "
        "{%0,%1,%2,%3}, {%4,%5,%6,%7}, {%8,%9}, {%0,%1,%2,%3};"
        : "+f"(c[0]), "+f"(c[1]), "+f"(c[2]), "+f"(c[3])
        : "r"(a0), "r"(a1), "r"(a2), "r"(a3), "r"(b0), "r"(b1));
}
__device__ __forceinline__ void mma_bf16(float c[4], uint32_t a0, uint32_t a1,
                                         uint32_t a2, uint32_t a3,
                                         uint32_t b0, uint32_t b1) {
    asm volatile(
        "mma.sync.aligned.m16n8k16.row.col.f32.bf16.bf16.f32 "
        "{%0,%1,%2,%3}, {%4,%5,%6,%7}, {%8,%9}, {%0,%1,%2,%3};"
        : "+f"(c[0]), "+f"(c[1]), "+f"(c[2]), "+f"(c[3])
        : "r"(a0), "r"(a1), "r"(a2), "r"(a3), "r"(b0), "r"(b1));
}
__device__ __forceinline__ void cpa16(uint32_t dst, const void* src) {
    asm volatile("cp.async.cg.shared.global [%0], [%1], 16;" :: "r"(dst), "l"(src) : "memory");
}
#define CP_COMMIT() asm volatile("cp.async.commit_group;" ::: "memory")
#define CP_WAIT1()  asm volatile("cp.async.wait_group 1;" ::: "memory")
#define CP_WAIT0()  asm volatile("cp.async.wait_group 0;" ::: "memory")

// =============================================================================
// Projection. sel 0/1 (Q/K, O=32): bf16 high/low split, kperm_bf layout.
// sel 2 (V, O=256): FUSED transpose -> writes g_V2[b][c][kperm(j)] directly,
// tf32-rounded (same rounding point as the old separate transpose kernel).
// =============================================================================
__global__ __launch_bounds__(256) void proj_kernel(
    const float* __restrict__ x, const float* __restrict__ Wm,
    const float* __restrict__ bias, int O, int sel)
{
    __shared__ float Xs[16][128];
    __shared__ float Ws[16][64];
    __shared__ float Vt[64 * 131];   // [c_local][i_local], stride 131 (sel==2)

    const int b  = blockIdx.z;
    const int i0 = blockIdx.x * 128;
    const int o0 = blockIdx.y * 64;
    const int t  = threadIdx.x;
    const int tx = t & 15;
    const int ty = t >> 4;

    const float* xb = x + (size_t)b * CDIM * NDIM;

    float acc[8][4];
#pragma unroll
    for (int r = 0; r < 8; r++)
#pragma unroll
        for (int u = 0; u < 4; u++) acc[r][u] = 0.f;

    for (int c0 = 0; c0 < CDIM; c0 += 16) {
#pragma unroll
        for (int l = t; l < 512; l += 256) {
            int r = l >> 5, q = l & 31;
            float4 v = *reinterpret_cast<const float4*>(xb + (size_t)(c0 + r) * NDIM + i0 + q * 4);
            *reinterpret_cast<float4*>(&Xs[r][q * 4]) = v;
        }
        {
            int o = t >> 2, c4 = (t & 3) * 4;
            float4 w = make_float4(0.f, 0.f, 0.f, 0.f);
            if (o0 + o < O)
                w = *reinterpret_cast<const float4*>(Wm + (size_t)(o0 + o) * CDIM + c0 + c4);
            Ws[c4 + 0][o] = w.x; Ws[c4 + 1][o] = w.y;
            Ws[c4 + 2][o] = w.z; Ws[c4 + 3][o] = w.w;
        }
        __syncthreads();
#pragma unroll
        for (int cc = 0; cc < 16; cc++) {
            float4 a0 = *reinterpret_cast<const float4*>(&Xs[cc][ty * 8]);
            float4 a1 = *reinterpret_cast<const float4*>(&Xs[cc][ty * 8 + 4]);
            float4 bv = *reinterpret_cast<const float4*>(&Ws[cc][tx * 4]);
            float aa[8] = {a0.x, a0.y, a0.z, a0.w, a1.x, a1.y, a1.z, a1.w};
            float bb[4] = {bv.x, bv.y, bv.z, bv.w};
#pragma unroll
            for (int r = 0; r < 8; r++)
#pragma unroll
                for (int u = 0; u < 4; u++) acc[r][u] += aa[r] * bb[u];
        }
        __syncthreads();
    }

    if (sel == 2) {
        // ---- fused transpose + kperm + tf32 round -> g_V2 ----
        float4 bs = *reinterpret_cast<const float4*>(bias + o0 + tx * 4);
        float bb[4] = {bs.x, bs.y, bs.z, bs.w};
#pragma unroll
        for (int r = 0; r < 8; r++)
#pragma unroll
            for (int u = 0; u < 4; u++)
                Vt[(tx * 4 + u) * 131 + ty * 8 + r] = acc[r][u] + bb[u];
        __syncthreads();

        const int lane = t & 31, grp = t >> 5;
        const int Bb = lane >> 1, h = lane & 1;
        // dst positions 4*lane..+3 <- sources (inverse of kperm within 8-block)
        const int s0 = 8 * Bb + (h ? 2 : 0);
        const int s1 = 8 * Bb + (h ? 6 : 4);
        const int s2 = 8 * Bb + (h ? 3 : 1);
        const int s3 = 8 * Bb + (h ? 7 : 5);
#pragma unroll
        for (int rr = 0; rr < 8; rr++) {
            const int c = grp + rr * 8;              // 0..63 local
            const float* row = &Vt[c * 131];
            float4 vv;
            vv.x = __uint_as_float(f2tf(row[s0]));
            vv.y = __uint_as_float(f2tf(row[s1]));
            vv.z = __uint_as_float(f2tf(row[s2]));
            vv.w = __uint_as_float(f2tf(row[s3]));
            *reinterpret_cast<float4*>(
                g_V2 + ((size_t)(b * CDIM + o0 + c) << 12) + i0 + lane * 4) = vv;
        }
    } else if (o0 + tx * 4 < O) {
        float4 bs = *reinterpret_cast<const float4*>(bias + o0 + tx * 4);
        float bb[4] = {bs.x, bs.y, bs.z, bs.w};
        __nv_bfloat16* Oh = (sel == 0) ? g_Qh : g_Kh;
        __nv_bfloat16* Ol = (sel == 0) ? g_Ql : g_Kl;
#pragma unroll
        for (int r = 0; r < 8; r++) {
            const size_t row = ((size_t)b * NDIM + i0 + ty * 8 + r) * 32;
#pragma unroll
            for (int u = 0; u < 4; u++) {
                float v = acc[r][u] + bb[u];
                __nv_bfloat16 hb = __float2bfloat16(v);
                __nv_bfloat16 lb = __float2bfloat16(v - __bfloat162float(hb));
                int pos = kperm_bf(tx * 4 + u);   // o0 == 0 for O=32
                Oh[row + pos] = hb;
                Ol[row + pos] = lb;
            }
        }
    }
}

// =============================================================================
// Flash attention: QK bf16-split m16n8k16, exp IN REGISTERS (no S roundtrip,
// 3 barriers/tile), PV tf32. 128-query CTAs, double-buffered K/V, 1 wave.
// Byte layout:
//   QH 0..8191 | QL 8192..16383 | K bufs 16384..32767 (2 x (KH 4K + KL 4K))
//   V 32768..163839 (2 x 64K) | P 163840..196607 | den 196608..197631
// =============================================================================
#define QH_B    0
#define QL_B    8192
#define K_B     16384
#define KBUF_B  8192      // per buffer: KH 4096 + KL 4096
#define V_F     8192      // float index (byte 32768)
#define VBUF_F  16384     // 256 x 64 floats
#define S_F     40960     // float index (byte 163840), 128 x 64 (P tile)
#define DEN_F   49152     // float index (byte 196608), 128 x 2
#define SMEM_ATTN 197632

__global__ __launch_bounds__(256, 1) void attn_kernel(
    const float* __restrict__ x, const float* __restrict__ gamma,
    float* __restrict__ out)
{
    extern __shared__ float smf[];
    char* smc = reinterpret_cast<char*>(smf);
    const uint32_t sb = smem_u32(smf);
    const int t  = threadIdx.x;
    const int w  = t >> 5;
    const int lg = (t & 31) >> 2;
    const int l4 = t & 3;
    const int b  = blockIdx.y;
    const int i0 = blockIdx.x * 128;

    // ---- Q preload: 128 rows x 4 chunks x {h,l} = 1024 16B-chunks ----
#pragma unroll
    for (int it = 0; it < 4; it++) {
        int idx = it * 256 + t;
        int arr = idx >> 9;              // 0 = Qh, 1 = Ql
        int r   = (idx >> 2) & 127;
        int q   = idx & 3;
        const __nv_bfloat16* src = (arr ? g_Ql : g_Qh)
            + ((size_t)(b * NDIM + i0 + r) << 5) + q * 8;
        char* dst = smc + (arr ? QL_B : QH_B) + r * 64 + (q ^ (r & 3)) * 16;
        *reinterpret_cast<uint4*>(dst) = *reinterpret_cast<const uint4*>(src);
    }

    auto fill = [&](int tl, int buf) {
        const int j0 = tl << 6;
        const uint32_t kb = sb + K_B + buf * KBUF_B;
        const uint32_t vb = sb + V_F * 4 + buf * VBUF_F * 4;
#pragma unroll
        for (int it = 0; it < 2; it++) {
            int idx = it * 256 + t;
            int arr = idx >> 8;          // 0 = Kh, 1 = Kl
            int r   = (idx >> 2) & 63;
            int q   = idx & 3;
            const __nv_bfloat16* src = (arr ? g_Kl : g_Kh)
                + ((size_t)(b * NDIM + j0 + r) << 5) + q * 8;
            cpa16(kb + arr * 4096 + r * 64 + (q ^ (r & 3)) * 16, src);
        }
#pragma unroll
        for (int it = 0; it < 16; it++) {
            int idx = it * 256 + t;
            int cr = idx >> 4, q = idx & 15;
            cpa16(vb + (cr * 64 + SWZ(cr, q * 4)) * 4,
                  g_V2 + ((size_t)(b * CDIM + cr) << 12) + j0 + q * 4);
        }
        CP_COMMIT();
    };

    fill(0, 0);

    // PV: warp tile rows pm0..+63, cols pn0..+63
    const int pm0 = (w & 1) * 64;
    const int pn0 = (w >> 1) * 64;
    float acc[4][8][4];
#pragma unroll
    for (int mt = 0; mt < 4; mt++)
#pragma unroll
        for (int nt = 0; nt < 8; nt++)
#pragma unroll
            for (int u = 0; u < 4; u++) acc[mt][nt][u] = 0.f;

    // QK: warp tile rows qm0..+31, cols qn0..+31
    const int qm0 = (w & 3) * 32;
    const int qn0 = (w >> 2) * 32;

    float den4[4] = {0.f, 0.f, 0.f, 0.f};   // per-thread row partials

    // P-store positions within 8-block for this thread's natural cols 2l4,2l4+1
    const int pos0 = (l4 < 2) ? (4 * l4)     : (4 * l4 - 7);
    const int pos1 = (l4 < 2) ? (4 * l4 + 2) : (4 * l4 - 5);

    for (int tl = 0; tl < 64; tl++) {
        const int buf = tl & 1;
        __syncthreads();                         // B0: PV(tl-1) P/V reads done
        if (tl < 63) { fill(tl + 1, buf ^ 1); CP_WAIT1(); }
        else         { CP_WAIT0(); }
        __syncthreads();                         // B1: tile tl K/V (and Q) visible

        // ---- S = Q.K^T (bf16 split) + exp in registers + P store ----
        {
            const char* khb = smc + K_B + buf * KBUF_B;
            const char* klb = khb + 4096;
            float sfrag[2][4][4];
#pragma unroll
            for (int mt = 0; mt < 2; mt++)
#pragma unroll
                for (int nt = 0; nt < 4; nt++)
#pragma unroll
                    for (int u = 0; u < 4; u++) sfrag[mt][nt][u] = 0.f;

#pragma unroll
            for (int kst = 0; kst < 2; kst++) {
                const int co = 32 * kst + 8 * l4;
                uint2 qh[2][2], ql[2][2];
#pragma unroll
                for (int mt = 0; mt < 2; mt++) {
                    const int r0 = qm0 + mt * 16;
                    const int rA = r0 + lg, rB = r0 + lg + 8;
                    qh[mt][0] = *reinterpret_cast<const uint2*>(smc + QH_B + rA * 64 + (co ^ (16 * (rA & 3))));
                    qh[mt][1] = *reinterpret_cast<const uint2*>(smc + QH_B + rB * 64 + (co ^ (16 * (rB & 3))));
                    ql[mt][0] = *reinterpret_cast<const uint2*>(smc + QL_B + rA * 64 + (co ^ (16 * (rA & 3))));
                    ql[mt][1] = *reinterpret_cast<const uint2*>(smc + QL_B + rB * 64 + (co ^ (16 * (rB & 3))));
                }
#pragma unroll
                for (int nt = 0; nt < 4; nt++) {
                    const int jr = qn0 + nt * 8 + lg;
                    const int koff = jr * 64 + (co ^ (16 * (jr & 3)));
                    uint2 bh = *reinterpret_cast<const uint2*>(khb + koff);
                    uint2 bl = *reinterpret_cast<const uint2*>(klb + koff);
#pragma unroll
                    for (int mt = 0; mt < 2; mt++) {
                        mma_bf16(sfrag[mt][nt], qh[mt][0].x, qh[mt][1].x, qh[mt][0].y, qh[mt][1].y, bh.x, bh.y);
                        mma_bf16(sfrag[mt][nt], qh[mt][0].x, qh[mt][1].x, qh[mt][0].y, qh[mt][1].y, bl.x, bl.y);
                        mma_bf16(sfrag[mt][nt], ql[mt][0].x, ql[mt][1].x, ql[mt][0].y, ql[mt][1].y, bh.x, bh.y);
                    }
                }
            }
            // exp + tf32 round + scatter to P (k-interleaved), den partials
            float dloc[4] = {0.f, 0.f, 0.f, 0.f};
#pragma unroll
            for (int mt = 0; mt < 2; mt++) {
                const int rA = qm0 + mt * 16 + lg;
                const int rB = rA + 8;
#pragma unroll
                for (int nt = 0; nt < 4; nt++) {
                    const int blk = qn0 + nt * 8;
                    float p0 = __uint_as_float(f2tf(__expf(sfrag[mt][nt][0])));
                    float p1 = __uint_as_float(f2tf(__expf(sfrag[mt][nt][1])));
                    float p2 = __uint_as_float(f2tf(__expf(sfrag[mt][nt][2])));
                    float p3 = __uint_as_float(f2tf(__expf(sfrag[mt][nt][3])));
                    dloc[mt * 2 + 0] += p0 + p1;
                    dloc[mt * 2 + 1] += p2 + p3;
                    smf[S_F + rA * 64 + SWZ(rA, blk + pos0)] = p0;
                    smf[S_F + rA * 64 + SWZ(rA, blk + pos1)] = p1;
                    smf[S_F + rB * 64 + SWZ(rB, blk + pos0)] = p2;
                    smf[S_F + rB * 64 + SWZ(rB, blk + pos1)] = p3;
                }
            }
#pragma unroll
            for (int m = 0; m < 4; m++) {        // reduce over l4 quad
                dloc[m] += __shfl_xor_sync(0xffffffffu, dloc[m], 1);
                dloc[m] += __shfl_xor_sync(0xffffffffu, dloc[m], 2);
                den4[m] += dloc[m];
            }
        }
        __syncthreads();                         // B3: P complete

        // ---- OUT += P.V  (tf32; M=128, N=256, K=64; warp 64x64) ----
        {
            const int vbb = V_F + buf * VBUF_F;
#pragma unroll
            for (int kst = 0; kst < 8; kst++) {
                const int k0 = kst * 8 + 2 * l4;
                const int ksw = SWZ(lg, k0);
                uint2 pa[4][2];
#pragma unroll
                for (int mt = 0; mt < 4; mt++) {
                    const int r0 = pm0 + mt * 16;
                    pa[mt][0] = *reinterpret_cast<const uint2*>(&smf[S_F + (r0 + lg)     * 64 + ksw]);
                    pa[mt][1] = *reinterpret_cast<const uint2*>(&smf[S_F + (r0 + lg + 8) * 64 + ksw]);
                }
#pragma unroll
                for (int nt = 0; nt < 8; nt++) {
                    const int cr = pn0 + nt * 8 + lg;
                    uint2 bv = *reinterpret_cast<const uint2*>(&smf[vbb + cr * 64 + ksw]);
#pragma unroll
                    for (int mt = 0; mt < 4; mt++)
                        mma_tf32(acc[mt][nt], pa[mt][0].x, pa[mt][1].x,
                                 pa[mt][0].y, pa[mt][1].y, bv.x, bv.y);
                }
            }
        }
    }

    // ---- den: write per-(row, col-half) partials, combine in epilogue ----
    if (l4 == 0) {
#pragma unroll
        for (int m = 0; m < 4; m++) {
            const int row = qm0 + (m >> 1) * 16 + lg + (m & 1) * 8;
            smf[DEN_F + row * 2 + (w >> 2)] = den4[m];
        }
    }
    __syncthreads();

    const float ga = gamma[0];
    const float* xb = x   + (size_t)b * CDIM * NDIM;
    float*       ob = out + (size_t)b * CDIM * NDIM;

#pragma unroll
    for (int mt = 0; mt < 4; mt++) {
        const int r0 = pm0 + mt * 16;
        const int rA = r0 + lg, rB = r0 + lg + 8;
        const float inv0 = 1.f / (smf[DEN_F + rA * 2] + smf[DEN_F + rA * 2 + 1]);
        const float inv1 = 1.f / (smf[DEN_F + rB * 2] + smf[DEN_F + rB * 2 + 1]);
        const int gi0 = i0 + rA;
#pragma unroll
        for (int nt = 0; nt < 8; nt++) {
            const int col = pn0 + nt * 8 + 2 * l4;
            const size_t b00 = (size_t)col * NDIM + gi0;
            const size_t b10 = b00 + NDIM;
            ob[b00]     = ga * (acc[mt][nt][0] * inv0) + xb[b00];
            ob[b10]     = ga * (acc[mt][nt][1] * inv0) + xb[b10];
            ob[b00 + 8] = ga * (acc[mt][nt][2] * inv1) + xb[b00 + 8];
            ob[b10 + 8] = ga * (acc[mt][nt][3] * inv1) + xb[b10 + 8];
        }
    }
}

// =============================================================================
extern "C" void kernel_launch(void* const* d_in, const int* in_sizes, int n_in,
                              void* d_out, int out_size)
{
    (void)in_sizes; (void)n_in; (void)out_size;
    const float* x     = (const float*)d_in[0];
    const float* Wq    = (const float*)d_in[1];
    const float* bq    = (const float*)d_in[2];
    const float* Wk    = (const float*)d_in[3];
    const float* bk    = (const float*)d_in[4];
    const float* Wv    = (const float*)d_in[5];
    const float* bv    = (const float*)d_in[6];
    const float* gamma = (const float*)d_in[7];
    float* out = (float*)d_out;

    (void)cudaFuncSetAttribute(attn_kernel,
                               cudaFuncAttributeMaxDynamicSharedMemorySize, SMEM_ATTN);

    dim3 gq(NDIM / 128, 1, BB);
    dim3 gv(NDIM / 128, 4, BB);
    proj_kernel<<<gq, 256>>>(x, Wq, bq, C8,   0);
    proj_kernel<<<gq, 256>>>(x, Wk, bk, C8,   1);
    proj_kernel<<<gv, 256>>>(x, Wv, bv, CDIM, 2);   // fused transpose -> g_V2

    dim3 ga(NDIM / 128, BB);    // 128 CTAs, occ 1 -> single wave
    attn_kernel<<<ga, 256, SMEM_ATTN>>>(x, gamma, out);
}